// round 1
// baseline (speedup 1.0000x reference)
#include <cuda_runtime.h>
#include <cuda_bf16.h>

// Problem constants
#define B_  4
#define N_  2048
#define C_  256
#define H_  8
#define D_  32
#define M_  (B_ * N_)          // 8192 rows
__device__ __constant__ float c_scale = 0.17677669529663689f; // 32^-0.5

// ---------------- scratch (no allocations allowed) ----------------
__device__ float g_q[(size_t)B_ * H_ * N_ * D_];   // [b][h][n][d], pre-scaled
__device__ float g_k[(size_t)B_ * H_ * N_ * D_];
__device__ float g_v[(size_t)B_ * H_ * N_ * D_];
__device__ __nv_bfloat16 g_bias[(size_t)H_ * N_ * N_];   // [h][n][m], 64MB
__device__ float g_ao[(size_t)B_ * N_ * C_];       // attn out [b][n][h*32+d]

// =====================================================================
// K1: QKV GEMM  X(8192x256) @ Wqkv(256x768) -> scatter into g_q/g_k/g_v
// 128x128 tile, BK=8, 256 threads, 8x8 per-thread microtile
// =====================================================================
__global__ __launch_bounds__(256) void k_qkv_gemm(
    const float* __restrict__ X, const float* __restrict__ W)
{
    __shared__ float As[8 * 128];   // transposed A tile
    __shared__ float Bs[8 * 128];

    const int tid = threadIdx.x;
    const int ct = blockIdx.x;      // 0..5  (col tile of 128 over 768)
    const int rt = blockIdx.y;      // 0..63 (row tile of 128 over 8192)

    const int ar = tid >> 1, ac4 = (tid & 1) * 4;   // A loader coords
    const int br = tid >> 5, bc4 = (tid & 31) * 4;  // B loader coords
    const int tx = tid & 15, ty = tid >> 4;         // 16x16 compute grid

    const float* Ap = X + (size_t)(rt * 128 + ar) * 256 + ac4;
    const float* Bp = W + (size_t)br * 768 + ct * 128 + bc4;

    float acc[8][8];
#pragma unroll
    for (int i = 0; i < 8; ++i)
#pragma unroll
        for (int j = 0; j < 8; ++j) acc[i][j] = 0.0f;

    for (int kt = 0; kt < 32; ++kt) {
        float4 av = *(const float4*)(Ap + kt * 8);
        float4 bv = *(const float4*)(Bp + (size_t)kt * 8 * 768);
        __syncthreads();
        As[(ac4 + 0) * 128 + ar] = av.x;
        As[(ac4 + 1) * 128 + ar] = av.y;
        As[(ac4 + 2) * 128 + ar] = av.z;
        As[(ac4 + 3) * 128 + ar] = av.w;
        *(float4*)(Bs + br * 128 + bc4) = bv;
        __syncthreads();
#pragma unroll
        for (int k = 0; k < 8; ++k) {
            float a[8], b[8];
            *(float4*)(a)     = *(const float4*)(As + k * 128 + ty * 8);
            *(float4*)(a + 4) = *(const float4*)(As + k * 128 + ty * 8 + 4);
            *(float4*)(b)     = *(const float4*)(Bs + k * 128 + tx * 8);
            *(float4*)(b + 4) = *(const float4*)(Bs + k * 128 + tx * 8 + 4);
#pragma unroll
            for (int i = 0; i < 8; ++i)
#pragma unroll
                for (int j = 0; j < 8; ++j) acc[i][j] += a[i] * b[j];
        }
    }

    // epilogue: scatter into q/k/v layout [b][h][n][d], scale q
    const int which = ct >> 1;                     // 0=q 1=k 2=v
    const float fac = (which == 0) ? c_scale : 1.0f;
    float* dst = (which == 0) ? g_q : (which == 1) ? g_k : g_v;
    const int cq0 = ct * 128 + tx * 8 - which * 256;   // 0..255, 8-aligned
    const int h = cq0 >> 5, d0 = cq0 & 31;
    const int b = (rt * 128) >> 11;                // whole tile in one batch
#pragma unroll
    for (int i = 0; i < 8; ++i) {
        const int row = rt * 128 + ty * 8 + i;
        const int n = row & (N_ - 1);
        float* p = dst + ((size_t)((b * H_ + h) * N_ + n)) * D_ + d0;
        float4 o0 = make_float4(acc[i][0] * fac, acc[i][1] * fac,
                                acc[i][2] * fac, acc[i][3] * fac);
        float4 o1 = make_float4(acc[i][4] * fac, acc[i][5] * fac,
                                acc[i][6] * fac, acc[i][7] * fac);
        *(float4*)(p)     = o0;
        *(float4*)(p + 4) = o1;
    }
}

// =====================================================================
// K2: bias materialization  g_bias[h][n][m] = table[rel[n*N+m]][h] (bf16)
// one thread handles 4 consecutive m
// =====================================================================
__global__ __launch_bounds__(256) void k_bias_gather(
    const int* __restrict__ rel, const float* __restrict__ table)
{
    const int t = blockIdx.x * 256 + threadIdx.x;  // 0 .. N*N/4-1
    const int n = t >> 9;                           // N/4 = 512 per row
    const int m4 = (t & 511) << 2;

    int4 id4 = *(const int4*)(rel + (size_t)n * N_ + m4);
    int ids[4] = {id4.x, id4.y, id4.z, id4.w};
    float v[4][8];
#pragma unroll
    for (int q = 0; q < 4; ++q) {
        const float4* tp = (const float4*)(table + (size_t)ids[q] * 8);
        float4 a = tp[0], c = tp[1];
        v[q][0] = a.x; v[q][1] = a.y; v[q][2] = a.z; v[q][3] = a.w;
        v[q][4] = c.x; v[q][5] = c.y; v[q][6] = c.z; v[q][7] = c.w;
    }
    const size_t base = (size_t)n * N_ + m4;
#pragma unroll
    for (int h = 0; h < 8; ++h) {
        __nv_bfloat162 lo = __floats2bfloat162_rn(v[0][h], v[1][h]);
        __nv_bfloat162 hi = __floats2bfloat162_rn(v[2][h], v[3][h]);
        __nv_bfloat162* p =
            (__nv_bfloat162*)(g_bias + (size_t)h * N_ * N_ + base);
        p[0] = lo;
        p[1] = hi;
    }
}

// =====================================================================
// K3: flash attention with bias.  grid (rowtile=32, h=8, b=4), 256 thr.
// Each warp owns 8 rows (two groups of 4). Lane owns cols {lane,lane+32}
// of the 64-col chunk and O[d=lane] for its rows.
// =====================================================================
__global__ __launch_bounds__(256) void k_attn()
{
    __shared__ float Qs[64 * 32];
    __shared__ float Ks[64 * 36];       // padded rows
    __shared__ float Vs[32 * 68];       // transposed [d][j], padded
    __shared__ float4 Pb[8][64];        // per-warp p broadcast, rows packed

    const int tid = threadIdx.x, wid = tid >> 5, lane = tid & 31;
    const int rt = blockIdx.x, h = blockIdx.y, b = blockIdx.z;
    const int row0 = rt * 64;

    const float* qg = g_q + ((size_t)((b * H_ + h) * N_ + row0)) * D_;
    const float* kg0 = g_k + ((size_t)((b * H_ + h) * N_)) * D_;
    const float* vg0 = g_v + ((size_t)((b * H_ + h) * N_)) * D_;

    for (int t2 = tid; t2 < 512; t2 += 256) {
        int j = t2 >> 3, d4 = (t2 & 7) << 2;
        *(float4*)(Qs + j * 32 + d4) = *(const float4*)(qg + j * 32 + d4);
    }

    float o[8], m[8], l[8];
#pragma unroll
    for (int r = 0; r < 8; ++r) { o[r] = 0.f; l[r] = 0.f; m[r] = -1e30f; }

    for (int c = 0; c < 32; ++c) {
        const int cb = c * 64;
        __syncthreads();
        const float* kg = kg0 + (size_t)cb * D_;
        const float* vg = vg0 + (size_t)cb * D_;
        for (int t2 = tid; t2 < 512; t2 += 256) {
            int j = t2 >> 3, d4 = (t2 & 7) << 2;
            float4 kv = *(const float4*)(kg + j * 32 + d4);
            *(float4*)(Ks + j * 36 + d4) = kv;
            float4 vv = *(const float4*)(vg + j * 32 + d4);
            Vs[(d4 + 0) * 68 + j] = vv.x;
            Vs[(d4 + 1) * 68 + j] = vv.y;
            Vs[(d4 + 2) * 68 + j] = vv.z;
            Vs[(d4 + 3) * 68 + j] = vv.w;
        }
        __syncthreads();

        const float4* Ks4 = (const float4*)Ks;
        const float4* Qs4 = (const float4*)Qs;
        const float4* Vs4 = (const float4*)Vs;
#pragma unroll
        for (int g = 0; g < 2; ++g) {
            const int rl0 = wid * 8 + g * 4;
            float s[4][2];
#pragma unroll
            for (int r = 0; r < 4; ++r) {
                size_t bi = ((size_t)(h * N_ + row0 + rl0 + r)) * N_ + cb;
                s[r][0] = __bfloat162float(g_bias[bi + lane]);
                s[r][1] = __bfloat162float(g_bias[bi + lane + 32]);
            }
#pragma unroll
            for (int i = 0; i < 8; ++i) {
                float4 k0 = Ks4[lane * 9 + i];
                float4 k1 = Ks4[(lane + 32) * 9 + i];
#pragma unroll
                for (int r = 0; r < 4; ++r) {
                    float4 qf = Qs4[(rl0 + r) * 8 + i];
                    s[r][0] += qf.x * k0.x + qf.y * k0.y + qf.z * k0.z + qf.w * k0.w;
                    s[r][1] += qf.x * k1.x + qf.y * k1.y + qf.z * k1.z + qf.w * k1.w;
                }
            }
            float p[4][2];
#pragma unroll
            for (int r = 0; r < 4; ++r) {
                const int ri = g * 4 + r;
                float mx = fmaxf(s[r][0], s[r][1]);
#pragma unroll
                for (int off = 16; off > 0; off >>= 1)
                    mx = fmaxf(mx, __shfl_xor_sync(0xffffffffu, mx, off));
                float mn = fmaxf(m[ri], mx);
                float alpha = __expf(m[ri] - mn);
                p[r][0] = __expf(s[r][0] - mn);
                p[r][1] = __expf(s[r][1] - mn);
                float ps = p[r][0] + p[r][1];
#pragma unroll
                for (int off = 16; off > 0; off >>= 1)
                    ps += __shfl_xor_sync(0xffffffffu, ps, off);
                l[ri] = l[ri] * alpha + ps;
                m[ri] = mn;
                o[ri] *= alpha;
            }
            Pb[wid][lane]      = make_float4(p[0][0], p[1][0], p[2][0], p[3][0]);
            Pb[wid][lane + 32] = make_float4(p[0][1], p[1][1], p[2][1], p[3][1]);
            __syncwarp();
#pragma unroll
            for (int jj = 0; jj < 16; ++jj) {
                float4 vv = Vs4[lane * 17 + jj];
                float4 pa = Pb[wid][jj * 4 + 0];
                float4 pb = Pb[wid][jj * 4 + 1];
                float4 pc = Pb[wid][jj * 4 + 2];
                float4 pd = Pb[wid][jj * 4 + 3];
                o[g * 4 + 0] += pa.x * vv.x + pb.x * vv.y + pc.x * vv.z + pd.x * vv.w;
                o[g * 4 + 1] += pa.y * vv.x + pb.y * vv.y + pc.y * vv.z + pd.y * vv.w;
                o[g * 4 + 2] += pa.z * vv.x + pb.z * vv.y + pc.z * vv.z + pd.z * vv.w;
                o[g * 4 + 3] += pa.w * vv.x + pb.w * vv.y + pc.w * vv.z + pd.w * vv.w;
            }
            __syncwarp();
        }
    }
    // epilogue: out[b][n][h*32 + d]
#pragma unroll
    for (int ri = 0; ri < 8; ++ri) {
        const int grow = row0 + wid * 8 + ri;
        g_ao[((size_t)(b * N_ + grow)) * C_ + h * D_ + lane] =
            o[ri] * (1.0f / l[ri]);
    }
}

// =====================================================================
// K4: out projection  g_ao(8192x256) @ Wout(256x256) + b_out -> d_out
// =====================================================================
__global__ __launch_bounds__(256) void k_out_gemm(
    const float* __restrict__ W, const float* __restrict__ bias,
    float* __restrict__ out)
{
    __shared__ float As[8 * 128];
    __shared__ float Bs[8 * 128];

    const int tid = threadIdx.x;
    const int ct = blockIdx.x;   // 0..1
    const int rt = blockIdx.y;   // 0..63

    const int ar = tid >> 1, ac4 = (tid & 1) * 4;
    const int br = tid >> 5, bc4 = (tid & 31) * 4;
    const int tx = tid & 15, ty = tid >> 4;

    const float* Ap = g_ao + (size_t)(rt * 128 + ar) * 256 + ac4;
    const float* Bp = W + (size_t)br * 256 + ct * 128 + bc4;

    float acc[8][8];
#pragma unroll
    for (int i = 0; i < 8; ++i)
#pragma unroll
        for (int j = 0; j < 8; ++j) acc[i][j] = 0.0f;

    for (int kt = 0; kt < 32; ++kt) {
        float4 av = *(const float4*)(Ap + kt * 8);
        float4 bv = *(const float4*)(Bp + (size_t)kt * 8 * 256);
        __syncthreads();
        As[(ac4 + 0) * 128 + ar] = av.x;
        As[(ac4 + 1) * 128 + ar] = av.y;
        As[(ac4 + 2) * 128 + ar] = av.z;
        As[(ac4 + 3) * 128 + ar] = av.w;
        *(float4*)(Bs + br * 128 + bc4) = bv;
        __syncthreads();
#pragma unroll
        for (int k = 0; k < 8; ++k) {
            float a[8], b[8];
            *(float4*)(a)     = *(const float4*)(As + k * 128 + ty * 8);
            *(float4*)(a + 4) = *(const float4*)(As + k * 128 + ty * 8 + 4);
            *(float4*)(b)     = *(const float4*)(Bs + k * 128 + tx * 8);
            *(float4*)(b + 4) = *(const float4*)(Bs + k * 128 + tx * 8 + 4);
#pragma unroll
            for (int i = 0; i < 8; ++i)
#pragma unroll
                for (int j = 0; j < 8; ++j) acc[i][j] += a[i] * b[j];
        }
    }

    const int col0 = ct * 128 + tx * 8;
    float4 bb0 = *(const float4*)(bias + col0);
    float4 bb1 = *(const float4*)(bias + col0 + 4);
#pragma unroll
    for (int i = 0; i < 8; ++i) {
        const int row = rt * 128 + ty * 8 + i;
        float* p = out + (size_t)row * 256 + col0;
        float4 o0 = make_float4(acc[i][0] + bb0.x, acc[i][1] + bb0.y,
                                acc[i][2] + bb0.z, acc[i][3] + bb0.w);
        float4 o1 = make_float4(acc[i][4] + bb1.x, acc[i][5] + bb1.y,
                                acc[i][6] + bb1.z, acc[i][7] + bb1.w);
        *(float4*)(p)     = o0;
        *(float4*)(p + 4) = o1;
    }
}

// =====================================================================
extern "C" void kernel_launch(void* const* d_in, const int* in_sizes, int n_in,
                              void* d_out, int out_size)
{
    const float* x          = (const float*)d_in[0];
    const float* w_qkv      = (const float*)d_in[1];
    const float* bias_table = (const float*)d_in[2];
    const float* w_out      = (const float*)d_in[3];
    const float* b_out      = (const float*)d_in[4];
    const int*   rel_index  = (const int*)d_in[5];
    float* out = (float*)d_out;

    k_qkv_gemm<<<dim3(6, 64), 256>>>(x, w_qkv);
    k_bias_gather<<<(N_ * N_ / 4) / 256, 256>>>(rel_index, bias_table);
    k_attn<<<dim3(N_ / 64, H_, B_), 256>>>();
    k_out_gemm<<<dim3(2, 64), 256>>>(w_out, b_out, out);
}

// round 3
// speedup vs baseline: 3.0679x; 3.0679x over previous
#include <cuda_runtime.h>
#include <cuda_bf16.h>
#include <cuda_fp16.h>
#include <cstdint>
#include <cstddef>

// Problem constants
#define B_  4
#define N_  2048
#define C_  256
#define H_  8
#define D_  32
__device__ __constant__ float c_scale = 0.17677669529663689f; // 32^-0.5

// ---------------- scratch (no allocations allowed) ----------------
__device__ float g_q[(size_t)B_ * H_ * N_ * D_];   // [b][h][n][d], pre-scaled
__device__ float g_k[(size_t)B_ * H_ * N_ * D_];
__device__ float g_v[(size_t)B_ * H_ * N_ * D_];
__device__ __nv_bfloat16 g_bias[(size_t)H_ * N_ * N_];   // [h][n][m], 64MB
__device__ float g_ao[(size_t)B_ * N_ * C_];       // attn out [b][n][h*32+d]

// ---------------- mma helpers ----------------
__device__ __forceinline__ uint32_t f2tf32(float f) {
    uint32_t r;
    asm("cvt.rna.tf32.f32 %0, %1;" : "=r"(r) : "f"(f));
    return r;
}
__device__ __forceinline__ void mma_tf32(float* c, const uint32_t* a,
                                         uint32_t b0, uint32_t b1) {
    asm("mma.sync.aligned.m16n8k8.row.col.f32.tf32.tf32.f32 "
        "{%0,%1,%2,%3},{%4,%5,%6,%7},{%8,%9},{%0,%1,%2,%3};"
        : "+f"(c[0]), "+f"(c[1]), "+f"(c[2]), "+f"(c[3])
        : "r"(a[0]), "r"(a[1]), "r"(a[2]), "r"(a[3]), "r"(b0), "r"(b1));
}
__device__ __forceinline__ void mma_f16(float* c, uint32_t a0, uint32_t a1,
                                        uint32_t a2, uint32_t a3,
                                        uint32_t b0, uint32_t b1) {
    asm("mma.sync.aligned.m16n8k16.row.col.f32.f16.f16.f32 "
        "{%0,%1,%2,%3},{%4,%5,%6,%7},{%8,%9},{%0,%1,%2,%3};"
        : "+f"(c[0]), "+f"(c[1]), "+f"(c[2]), "+f"(c[3])
        : "r"(a0), "r"(a1), "r"(a2), "r"(a3), "r"(b0), "r"(b1));
}
__device__ __forceinline__ uint32_t packh2(float x, float y) {
    __half2 h = __floats2half2_rn(x, y);
    return *(uint32_t*)&h;
}

// =====================================================================
// K1: QKV GEMM  X(8192x256) @ Wqkv(256x768) -> scatter into g_q/g_k/g_v
// =====================================================================
__global__ __launch_bounds__(256) void k_qkv_gemm(
    const float* __restrict__ X, const float* __restrict__ W)
{
    __shared__ float As[8 * 128];
    __shared__ float Bs[8 * 128];

    const int tid = threadIdx.x;
    const int ct = blockIdx.x;      // 0..5
    const int rt = blockIdx.y;      // 0..63

    const int ar = tid >> 1, ac4 = (tid & 1) * 4;
    const int br = tid >> 5, bc4 = (tid & 31) * 4;
    const int tx = tid & 15, ty = tid >> 4;

    const float* Ap = X + (size_t)(rt * 128 + ar) * 256 + ac4;
    const float* Bp = W + (size_t)br * 768 + ct * 128 + bc4;

    float acc[8][8];
#pragma unroll
    for (int i = 0; i < 8; ++i)
#pragma unroll
        for (int j = 0; j < 8; ++j) acc[i][j] = 0.0f;

    for (int kt = 0; kt < 32; ++kt) {
        float4 av = *(const float4*)(Ap + kt * 8);
        float4 bv = *(const float4*)(Bp + (size_t)kt * 8 * 768);
        __syncthreads();
        As[(ac4 + 0) * 128 + ar] = av.x;
        As[(ac4 + 1) * 128 + ar] = av.y;
        As[(ac4 + 2) * 128 + ar] = av.z;
        As[(ac4 + 3) * 128 + ar] = av.w;
        *(float4*)(Bs + br * 128 + bc4) = bv;
        __syncthreads();
#pragma unroll
        for (int k = 0; k < 8; ++k) {
            float a[8], b[8];
            *(float4*)(a)     = *(const float4*)(As + k * 128 + ty * 8);
            *(float4*)(a + 4) = *(const float4*)(As + k * 128 + ty * 8 + 4);
            *(float4*)(b)     = *(const float4*)(Bs + k * 128 + tx * 8);
            *(float4*)(b + 4) = *(const float4*)(Bs + k * 128 + tx * 8 + 4);
#pragma unroll
            for (int i = 0; i < 8; ++i)
#pragma unroll
                for (int j = 0; j < 8; ++j) acc[i][j] += a[i] * b[j];
        }
    }

    const int which = ct >> 1;                     // 0=q 1=k 2=v
    const float fac = (which == 0) ? c_scale : 1.0f;
    float* dst = (which == 0) ? g_q : (which == 1) ? g_k : g_v;
    const int cq0 = ct * 128 + tx * 8 - which * 256;
    const int h = cq0 >> 5, d0 = cq0 & 31;
    const int b = (rt * 128) >> 11;
#pragma unroll
    for (int i = 0; i < 8; ++i) {
        const int row = rt * 128 + ty * 8 + i;
        const int n = row & (N_ - 1);
        float* p = dst + ((size_t)((b * H_ + h) * N_ + n)) * D_ + d0;
        float4 o0 = make_float4(acc[i][0] * fac, acc[i][1] * fac,
                                acc[i][2] * fac, acc[i][3] * fac);
        float4 o1 = make_float4(acc[i][4] * fac, acc[i][5] * fac,
                                acc[i][6] * fac, acc[i][7] * fac);
        *(float4*)(p)     = o0;
        *(float4*)(p + 4) = o1;
    }
}

// =====================================================================
// K2: bias materialization g_bias[h][n][m] = table[rel[n*N+m]][h] (bf16)
// =====================================================================
__global__ __launch_bounds__(256) void k_bias_gather(
    const int* __restrict__ rel, const float* __restrict__ table)
{
    const int t = blockIdx.x * 256 + threadIdx.x;
    const int n = t >> 9;
    const int m4 = (t & 511) << 2;

    int4 id4 = *(const int4*)(rel + (size_t)n * N_ + m4);
    int ids[4] = {id4.x, id4.y, id4.z, id4.w};
    float v[4][8];
#pragma unroll
    for (int q = 0; q < 4; ++q) {
        const float4* tp = (const float4*)(table + (size_t)ids[q] * 8);
        float4 a = tp[0], c = tp[1];
        v[q][0] = a.x; v[q][1] = a.y; v[q][2] = a.z; v[q][3] = a.w;
        v[q][4] = c.x; v[q][5] = c.y; v[q][6] = c.z; v[q][7] = c.w;
    }
    const size_t base = (size_t)n * N_ + m4;
#pragma unroll
    for (int h = 0; h < 8; ++h) {
        __nv_bfloat162 lo = __floats2bfloat162_rn(v[0][h], v[1][h]);
        __nv_bfloat162 hi = __floats2bfloat162_rn(v[2][h], v[3][h]);
        __nv_bfloat162* p =
            (__nv_bfloat162*)(g_bias + (size_t)h * N_ * N_ + base);
        p[0] = lo;
        p[1] = hi;
    }
}

// =====================================================================
// K3: tensor-core flash attention with bias.
// Block = 8 warps, each warp 16 q-rows (Br=128), Bc=64 keys/chunk.
// QK^T: mma.m16n8k8 tf32.  PV: mma.m16n8k16 fp16 (P from S regs).
// Bias preloaded into S accumulators (init value).
// =====================================================================
__global__ __launch_bounds__(256) void k_attn_mma()
{
    __shared__ float         Ks[64 * 36];        // K chunk, tf32 bits, pad 36
    __shared__ __half        Vt[32 * 72];        // V chunk transposed [d][j]
    __shared__ __nv_bfloat16 Bsm[128 * 72];      // bias tile [qrow][key], pad 72

    const int tid = threadIdx.x, wid = tid >> 5, lane = tid & 31;
    const int g = lane >> 2, i = lane & 3;       // groupID, tid-in-group
    const int rt = blockIdx.x, h = blockIdx.y, b = blockIdx.z;
    const int row0 = rt * 128;
    const int wr0 = wid * 16;

    const float* qg  = g_q + ((size_t)((b * H_ + h) * N_ + row0 + wr0)) * D_;
    const float* kg0 = g_k + ((size_t)((b * H_ + h) * N_)) * D_;
    const float* vg0 = g_v + ((size_t)((b * H_ + h) * N_)) * D_;
    const __nv_bfloat16* bg = g_bias + ((size_t)(h * N_ + row0)) * N_;

    // --- Q fragments (tf32), resident whole kernel ---
    uint32_t qa[4][4];
#pragma unroll
    for (int kk = 0; kk < 4; ++kk) {
        qa[kk][0] = f2tf32(qg[(size_t)g * 32 + i + 8 * kk]);
        qa[kk][1] = f2tf32(qg[(size_t)(g + 8) * 32 + i + 8 * kk]);
        qa[kk][2] = f2tf32(qg[(size_t)g * 32 + i + 4 + 8 * kk]);
        qa[kk][3] = f2tf32(qg[(size_t)(g + 8) * 32 + i + 4 + 8 * kk]);
    }

    float oc[4][4];
#pragma unroll
    for (int jn = 0; jn < 4; ++jn)
#pragma unroll
        for (int q = 0; q < 4; ++q) oc[jn][q] = 0.0f;
    float m0 = -1e30f, m1 = -1e30f, l0 = 0.0f, l1 = 0.0f;

    for (int cc = 0; cc < 32; ++cc) {
        const int cb = cc * 64;
        __syncthreads();
        // --- stage K (as tf32 bits) and V (transposed half) ---
#pragma unroll
        for (int it = 0; it < 2; ++it) {
            const int f4 = tid + 256 * it;
            const int j = f4 >> 3, d4 = (f4 & 7) << 2;
            float4 kv = *(const float4*)(kg0 + (size_t)(cb + j) * 32 + d4);
            uint4 kt;
            kt.x = f2tf32(kv.x); kt.y = f2tf32(kv.y);
            kt.z = f2tf32(kv.z); kt.w = f2tf32(kv.w);
            *(uint4*)(Ks + j * 36 + d4) = kt;
            float4 vv = *(const float4*)(vg0 + (size_t)(cb + j) * 32 + d4);
            Vt[(d4 + 0) * 72 + j] = __float2half(vv.x);
            Vt[(d4 + 1) * 72 + j] = __float2half(vv.y);
            Vt[(d4 + 2) * 72 + j] = __float2half(vv.z);
            Vt[(d4 + 3) * 72 + j] = __float2half(vv.w);
        }
        // --- stage bias tile (128 x 64 bf16) ---
#pragma unroll
        for (int it = 0; it < 4; ++it) {
            const int f4 = tid + 256 * it;
            const int r = f4 >> 3, c8 = (f4 & 7) << 3;
            float4 bb = *(const float4*)(bg + (size_t)r * N_ + cb + c8);
            *(float4*)((char*)Bsm + r * 144 + c8 * 2) = bb;
        }
        __syncthreads();

        // --- S = bias + Q K^T ---
        float cS[8][4];
#pragma unroll
        for (int j = 0; j < 8; ++j) {
            __nv_bfloat162 t0 = *(__nv_bfloat162*)(Bsm + (wr0 + g) * 72 + 8 * j + 2 * i);
            __nv_bfloat162 t1 = *(__nv_bfloat162*)(Bsm + (wr0 + g + 8) * 72 + 8 * j + 2 * i);
            float2 f0 = __bfloat1622float2(t0);
            float2 f1 = __bfloat1622float2(t1);
            cS[j][0] = f0.x; cS[j][1] = f0.y;
            cS[j][2] = f1.x; cS[j][3] = f1.y;
        }
#pragma unroll
        for (int j = 0; j < 8; ++j) {
#pragma unroll
            for (int kk = 0; kk < 4; ++kk) {
                uint32_t b0 = *(uint32_t*)(Ks + (g + 8 * j) * 36 + i + 8 * kk);
                uint32_t b1 = *(uint32_t*)(Ks + (g + 8 * j) * 36 + i + 4 + 8 * kk);
                mma_tf32(cS[j], qa[kk], b0, b1);
            }
        }

        // --- online softmax (rows g and g+8) ---
        float mx0 = -1e30f, mx1 = -1e30f;
#pragma unroll
        for (int j = 0; j < 8; ++j) {
            mx0 = fmaxf(mx0, fmaxf(cS[j][0], cS[j][1]));
            mx1 = fmaxf(mx1, fmaxf(cS[j][2], cS[j][3]));
        }
        mx0 = fmaxf(mx0, __shfl_xor_sync(0xffffffffu, mx0, 1));
        mx0 = fmaxf(mx0, __shfl_xor_sync(0xffffffffu, mx0, 2));
        mx1 = fmaxf(mx1, __shfl_xor_sync(0xffffffffu, mx1, 1));
        mx1 = fmaxf(mx1, __shfl_xor_sync(0xffffffffu, mx1, 2));

        const float nm0 = fmaxf(m0, mx0), nm1 = fmaxf(m1, mx1);
        const float al0 = __expf(m0 - nm0), al1 = __expf(m1 - nm1);
        float s0 = 0.0f, s1 = 0.0f;
#pragma unroll
        for (int j = 0; j < 8; ++j) {
            cS[j][0] = __expf(cS[j][0] - nm0);
            cS[j][1] = __expf(cS[j][1] - nm0);
            cS[j][2] = __expf(cS[j][2] - nm1);
            cS[j][3] = __expf(cS[j][3] - nm1);
            s0 += cS[j][0] + cS[j][1];
            s1 += cS[j][2] + cS[j][3];
        }
        s0 += __shfl_xor_sync(0xffffffffu, s0, 1);
        s0 += __shfl_xor_sync(0xffffffffu, s0, 2);
        s1 += __shfl_xor_sync(0xffffffffu, s1, 1);
        s1 += __shfl_xor_sync(0xffffffffu, s1, 2);
        l0 = l0 * al0 + s0;
        l1 = l1 * al1 + s1;
        m0 = nm0; m1 = nm1;
#pragma unroll
        for (int jn = 0; jn < 4; ++jn) {
            oc[jn][0] *= al0; oc[jn][1] *= al0;
            oc[jn][2] *= al1; oc[jn][3] *= al1;
        }

        // --- O += P V  (P straight from S registers, fp16) ---
#pragma unroll
        for (int kk = 0; kk < 4; ++kk) {
            uint32_t a0 = packh2(cS[2 * kk][0], cS[2 * kk][1]);
            uint32_t a1 = packh2(cS[2 * kk][2], cS[2 * kk][3]);
            uint32_t a2 = packh2(cS[2 * kk + 1][0], cS[2 * kk + 1][1]);
            uint32_t a3 = packh2(cS[2 * kk + 1][2], cS[2 * kk + 1][3]);
#pragma unroll
            for (int jn = 0; jn < 4; ++jn) {
                uint32_t b0 = *(uint32_t*)(Vt + (g + 8 * jn) * 72 + 2 * i + 16 * kk);
                uint32_t b1 = *(uint32_t*)(Vt + (g + 8 * jn) * 72 + 2 * i + 8 + 16 * kk);
                mma_f16(oc[jn], a0, a1, a2, a3, b0, b1);
            }
        }
    }

    // --- epilogue: g_ao[b][n][h*32+d] ---
    const float r0i = 1.0f / l0, r1i = 1.0f / l1;
    const int gr0 = row0 + wr0 + g;
#pragma unroll
    for (int jn = 0; jn < 4; ++jn) {
        const int col = h * D_ + 8 * jn + 2 * i;
        float2 v0 = make_float2(oc[jn][0] * r0i, oc[jn][1] * r0i);
        float2 v1 = make_float2(oc[jn][2] * r1i, oc[jn][3] * r1i);
        *(float2*)(g_ao + (size_t)(b * N_ + gr0) * C_ + col)       = v0;
        *(float2*)(g_ao + (size_t)(b * N_ + gr0 + 8) * C_ + col)   = v1;
    }
}

// =====================================================================
// K4: out projection  g_ao(8192x256) @ Wout(256x256) + b_out -> d_out
// =====================================================================
__global__ __launch_bounds__(256) void k_out_gemm(
    const float* __restrict__ W, const float* __restrict__ bias,
    float* __restrict__ out)
{
    __shared__ float As[8 * 128];
    __shared__ float Bs[8 * 128];

    const int tid = threadIdx.x;
    const int ct = blockIdx.x;   // 0..1
    const int rt = blockIdx.y;   // 0..63

    const int ar = tid >> 1, ac4 = (tid & 1) * 4;
    const int br = tid >> 5, bc4 = (tid & 31) * 4;
    const int tx = tid & 15, ty = tid >> 4;

    const float* Ap = g_ao + (size_t)(rt * 128 + ar) * 256 + ac4;
    const float* Bp = W + (size_t)br * 256 + ct * 128 + bc4;

    float acc[8][8];
#pragma unroll
    for (int i = 0; i < 8; ++i)
#pragma unroll
        for (int j = 0; j < 8; ++j) acc[i][j] = 0.0f;

    for (int kt = 0; kt < 32; ++kt) {
        float4 av = *(const float4*)(Ap + kt * 8);
        float4 bv = *(const float4*)(Bp + (size_t)kt * 8 * 256);
        __syncthreads();
        As[(ac4 + 0) * 128 + ar] = av.x;
        As[(ac4 + 1) * 128 + ar] = av.y;
        As[(ac4 + 2) * 128 + ar] = av.z;
        As[(ac4 + 3) * 128 + ar] = av.w;
        *(float4*)(Bs + br * 128 + bc4) = bv;
        __syncthreads();
#pragma unroll
        for (int k = 0; k < 8; ++k) {
            float a[8], b[8];
            *(float4*)(a)     = *(const float4*)(As + k * 128 + ty * 8);
            *(float4*)(a + 4) = *(const float4*)(As + k * 128 + ty * 8 + 4);
            *(float4*)(b)     = *(const float4*)(Bs + k * 128 + tx * 8);
            *(float4*)(b + 4) = *(const float4*)(Bs + k * 128 + tx * 8 + 4);
#pragma unroll
            for (int i = 0; i < 8; ++i)
#pragma unroll
                for (int j = 0; j < 8; ++j) acc[i][j] += a[i] * b[j];
        }
    }

    const int col0 = ct * 128 + tx * 8;
    float4 bb0 = *(const float4*)(bias + col0);
    float4 bb1 = *(const float4*)(bias + col0 + 4);
#pragma unroll
    for (int i = 0; i < 8; ++i) {
        const int row = rt * 128 + ty * 8 + i;
        float* p = out + (size_t)row * 256 + col0;
        float4 o0 = make_float4(acc[i][0] + bb0.x, acc[i][1] + bb0.y,
                                acc[i][2] + bb0.z, acc[i][3] + bb0.w);
        float4 o1 = make_float4(acc[i][4] + bb1.x, acc[i][5] + bb1.y,
                                acc[i][6] + bb1.z, acc[i][7] + bb1.w);
        *(float4*)(p)     = o0;
        *(float4*)(p + 4) = o1;
    }
}

// =====================================================================
extern "C" void kernel_launch(void* const* d_in, const int* in_sizes, int n_in,
                              void* d_out, int out_size)
{
    const float* x          = (const float*)d_in[0];
    const float* w_qkv      = (const float*)d_in[1];
    const float* bias_table = (const float*)d_in[2];
    const float* w_out      = (const float*)d_in[3];
    const float* b_out      = (const float*)d_in[4];
    const int*   rel_index  = (const int*)d_in[5];
    float* out = (float*)d_out;

    k_qkv_gemm<<<dim3(6, 64), 256>>>(x, w_qkv);
    k_bias_gather<<<(N_ * N_ / 4) / 256, 256>>>(rel_index, bias_table);
    k_attn_mma<<<dim3(N_ / 128, H_, B_), 256>>>();
    k_out_gemm<<<dim3(2, 64), 256>>>(w_out, b_out, out);
}

// round 8
// speedup vs baseline: 3.4706x; 1.1313x over previous
#include <cuda_runtime.h>
#include <cuda_bf16.h>
#include <cuda_fp16.h>
#include <cstdint>
#include <cstddef>

#define B_  4
#define N_  2048
#define C_  256
#define H_  8
#define D_  32
#define QK_SCALE 0.17677669529663689f

// ---------------- scratch ----------------
__device__ __half g_qh[(size_t)B_ * H_ * N_ * D_];   // pre-scaled
__device__ __half g_kh[(size_t)B_ * H_ * N_ * D_];
__device__ __half g_vh[(size_t)B_ * H_ * N_ * D_];
__device__ __nv_bfloat16 g_bias[(size_t)H_ * N_ * N_];
__device__ float g_ao[(size_t)B_ * N_ * C_];

// ---------------- mma helpers ----------------
__device__ __forceinline__ uint32_t f2tf32(float f) {
    uint32_t r;
    asm("cvt.rna.tf32.f32 %0, %1;" : "=r"(r) : "f"(f));
    return r;
}
__device__ __forceinline__ float tf32hi(float f) {
    return __uint_as_float(f2tf32(f));
}
__device__ __forceinline__ void mma_tf32(float* c, const uint32_t* a,
                                         uint32_t b0, uint32_t b1) {
    asm("mma.sync.aligned.m16n8k8.row.col.f32.tf32.tf32.f32 "
        "{%0,%1,%2,%3},{%4,%5,%6,%7},{%8,%9},{%0,%1,%2,%3};"
        : "+f"(c[0]), "+f"(c[1]), "+f"(c[2]), "+f"(c[3])
        : "r"(a[0]), "r"(a[1]), "r"(a[2]), "r"(a[3]), "r"(b0), "r"(b1));
}
__device__ __forceinline__ void mma_f16(float* c, uint32_t a0, uint32_t a1,
                                        uint32_t a2, uint32_t a3,
                                        uint32_t b0, uint32_t b1) {
    asm("mma.sync.aligned.m16n8k16.row.col.f32.f16.f16.f32 "
        "{%0,%1,%2,%3},{%4,%5,%6,%7},{%8,%9},{%0,%1,%2,%3};"
        : "+f"(c[0]), "+f"(c[1]), "+f"(c[2]), "+f"(c[3])
        : "r"(a0), "r"(a1), "r"(a2), "r"(a3), "r"(b0), "r"(b1));
}
__device__ __forceinline__ uint32_t packh2(float x, float y) {
    uint32_t r;
    asm("cvt.rn.f16x2.f32 %0, %1, %2;" : "=r"(r) : "f"(y), "f"(x));
    return r;
}

// =====================================================================
// tf32x3 GEMM: A(Mx256) @ B(256xN), block 128x64, 8 warps (4M x 2N)
// WHICH=0: A from param, QKV epilogue (fp16 scatter).
// WHICH=1: A = g_ao (bound in DEVICE code), out + bias epilogue (fp32).
// =====================================================================
template<int BSTRIDE, int WHICH>
__global__ __launch_bounds__(256) void k_gemm_tf32(
    const float* __restrict__ A, const float* __restrict__ Bw,
    const float* __restrict__ bias, float* __restrict__ out)
{
    __shared__ float Ah[16 * 136], Al[16 * 136];
    __shared__ float Bh[16 * 72],  Bl[16 * 72];

    const float* __restrict__ Asrc = (WHICH == 1) ? (const float*)g_ao : A;

    const int tid = threadIdx.x, wid = tid >> 5, lane = tid & 31;
    const int g = lane >> 2, i = lane & 3;
    const int bx = blockIdx.x, by = blockIdx.y;
    const int wm = (wid & 3) * 32, wn = (wid >> 2) * 32;

    float acc[2][4][4];
#pragma unroll
    for (int mt = 0; mt < 2; ++mt)
#pragma unroll
        for (int nt = 0; nt < 4; ++nt)
#pragma unroll
            for (int q = 0; q < 4; ++q) acc[mt][nt][q] = 0.0f;

    for (int kc = 0; kc < 256; kc += 16) {
        __syncthreads();
#pragma unroll
        for (int it = 0; it < 2; ++it) {
            const int f = tid + 256 * it;
            const int r = f >> 2, c4 = (f & 3) * 4;
            float4 av = *(const float4*)(Asrc + (size_t)(by * 128 + r) * 256 + kc + c4);
            float h0 = tf32hi(av.x), h1 = tf32hi(av.y);
            float h2 = tf32hi(av.z), h3 = tf32hi(av.w);
            Ah[(c4 + 0) * 136 + r] = h0;
            Ah[(c4 + 1) * 136 + r] = h1;
            Ah[(c4 + 2) * 136 + r] = h2;
            Ah[(c4 + 3) * 136 + r] = h3;
            Al[(c4 + 0) * 136 + r] = tf32hi(av.x - h0);
            Al[(c4 + 1) * 136 + r] = tf32hi(av.y - h1);
            Al[(c4 + 2) * 136 + r] = tf32hi(av.z - h2);
            Al[(c4 + 3) * 136 + r] = tf32hi(av.w - h3);
        }
        {
            const int kr = tid >> 4, nc4 = (tid & 15) * 4;
            float4 bv = *(const float4*)(Bw + (size_t)(kc + kr) * BSTRIDE + bx * 64 + nc4);
            float4 hv, lv;
            hv.x = tf32hi(bv.x); hv.y = tf32hi(bv.y);
            hv.z = tf32hi(bv.z); hv.w = tf32hi(bv.w);
            lv.x = tf32hi(bv.x - hv.x); lv.y = tf32hi(bv.y - hv.y);
            lv.z = tf32hi(bv.z - hv.z); lv.w = tf32hi(bv.w - hv.w);
            *(float4*)(Bh + kr * 72 + nc4) = hv;
            *(float4*)(Bl + kr * 72 + nc4) = lv;
        }
        __syncthreads();
#pragma unroll
        for (int s = 0; s < 2; ++s) {
            uint32_t ah[2][4], al[2][4];
#pragma unroll
            for (int mt = 0; mt < 2; ++mt) {
                const int mr = wm + 16 * mt + g;
                ah[mt][0] = __float_as_uint(Ah[(8 * s + i) * 136 + mr]);
                ah[mt][1] = __float_as_uint(Ah[(8 * s + i) * 136 + mr + 8]);
                ah[mt][2] = __float_as_uint(Ah[(8 * s + i + 4) * 136 + mr]);
                ah[mt][3] = __float_as_uint(Ah[(8 * s + i + 4) * 136 + mr + 8]);
                al[mt][0] = __float_as_uint(Al[(8 * s + i) * 136 + mr]);
                al[mt][1] = __float_as_uint(Al[(8 * s + i) * 136 + mr + 8]);
                al[mt][2] = __float_as_uint(Al[(8 * s + i + 4) * 136 + mr]);
                al[mt][3] = __float_as_uint(Al[(8 * s + i + 4) * 136 + mr + 8]);
            }
            uint32_t bh[4][2], bl[4][2];
#pragma unroll
            for (int nt = 0; nt < 4; ++nt) {
                const int nc = wn + 8 * nt + g;
                bh[nt][0] = __float_as_uint(Bh[(8 * s + i) * 72 + nc]);
                bh[nt][1] = __float_as_uint(Bh[(8 * s + i + 4) * 72 + nc]);
                bl[nt][0] = __float_as_uint(Bl[(8 * s + i) * 72 + nc]);
                bl[nt][1] = __float_as_uint(Bl[(8 * s + i + 4) * 72 + nc]);
            }
#pragma unroll
            for (int mt = 0; mt < 2; ++mt)
#pragma unroll
                for (int nt = 0; nt < 4; ++nt) {
                    mma_tf32(acc[mt][nt], ah[mt], bh[nt][0], bh[nt][1]);
                    mma_tf32(acc[mt][nt], ah[mt], bl[nt][0], bl[nt][1]);
                    mma_tf32(acc[mt][nt], al[mt], bh[nt][0], bh[nt][1]);
                }
        }
    }

    if (WHICH == 0) {
        // scatter to fp16 q/k/v [b][h][n][d], scale q
#pragma unroll
        for (int nt = 0; nt < 4; ++nt) {
            const int col = bx * 64 + wn + 8 * nt + 2 * i;
            const int which = col >> 8;
            const int cq = col & 255;
            const int hh = cq >> 5, dd = cq & 31;
            const float fac = (which == 0) ? QK_SCALE : 1.0f;
            __half* dst = (which == 0) ? g_qh : (which == 1) ? g_kh : g_vh;
#pragma unroll
            for (int mt = 0; mt < 2; ++mt) {
                const int m = by * 128 + wm + 16 * mt + g;
                const int b = m >> 11, n = m & (N_ - 1);
                __half* p0 = dst + ((size_t)((b * H_ + hh) * N_ + n)) * D_ + dd;
                __half* p1 = dst + ((size_t)((b * H_ + hh) * N_ + n + 8)) * D_ + dd;
                *(__half2*)p0 = __floats2half2_rn(acc[mt][nt][0] * fac, acc[mt][nt][1] * fac);
                *(__half2*)p1 = __floats2half2_rn(acc[mt][nt][2] * fac, acc[mt][nt][3] * fac);
            }
        }
    } else {
#pragma unroll
        for (int nt = 0; nt < 4; ++nt) {
            const int col = bx * 64 + wn + 8 * nt + 2 * i;
            const float bz0 = bias[col], bz1 = bias[col + 1];
#pragma unroll
            for (int mt = 0; mt < 2; ++mt) {
                const int m = by * 128 + wm + 16 * mt + g;
                *(float2*)(out + (size_t)m * 256 + col) =
                    make_float2(acc[mt][nt][0] + bz0, acc[mt][nt][1] + bz1);
                *(float2*)(out + (size_t)(m + 8) * 256 + col) =
                    make_float2(acc[mt][nt][2] + bz0, acc[mt][nt][3] + bz1);
            }
        }
    }
}

// =====================================================================
// bias gather (proven round-3 version): 4 m per thread
// =====================================================================
__global__ __launch_bounds__(256) void k_bias_gather(
    const int* __restrict__ rel, const float* __restrict__ table)
{
    const int t = blockIdx.x * 256 + threadIdx.x;  // 0 .. N*N/4-1
    const int n = t >> 9;
    const int m4 = (t & 511) << 2;

    int4 id4 = *(const int4*)(rel + (size_t)n * N_ + m4);
    int ids[4] = {id4.x, id4.y, id4.z, id4.w};
    float v[4][8];
#pragma unroll
    for (int q = 0; q < 4; ++q) {
        const float4* tp = (const float4*)(table + (size_t)ids[q] * 8);
        float4 a = tp[0], c = tp[1];
        v[q][0] = a.x; v[q][1] = a.y; v[q][2] = a.z; v[q][3] = a.w;
        v[q][4] = c.x; v[q][5] = c.y; v[q][6] = c.z; v[q][7] = c.w;
    }
    const size_t base = (size_t)n * N_ + m4;
#pragma unroll
    for (int h = 0; h < 8; ++h) {
        __nv_bfloat162 lo = __floats2bfloat162_rn(v[0][h], v[1][h]);
        __nv_bfloat162 hi = __floats2bfloat162_rn(v[2][h], v[3][h]);
        __nv_bfloat162* p =
            (__nv_bfloat162*)(g_bias + (size_t)h * N_ * N_ + base);
        p[0] = lo;
        p[1] = hi;
    }
}

// =====================================================================
// fp16 flash attention, 2 batches fused per block.
// grid (rt=16, h=8, bpair=2), 256 thr, 8 warps x 16 q-rows = 128 rows.
// Ks rows = keys (32 dims wide, stride LDK); Vt rows = dims (64 keys
// wide, stride LDV). Distinct strides — LDV >= 64 is load-bearing.
// =====================================================================
#define LDK 40
#define LDV 72

__global__ __launch_bounds__(256) void k_attn2()
{
    __shared__ __half Ks[2 * 64 * LDK];
    __shared__ __half Vt[2 * 32 * LDV];
    __shared__ __nv_bfloat16 Bsm[128 * 72];

    const int tid = threadIdx.x, wid = tid >> 5, lane = tid & 31;
    const int g = lane >> 2, i = lane & 3;
    const int rt = blockIdx.x, h = blockIdx.y, bz = blockIdx.z;
    const int b0i = bz * 2;
    const int row0 = rt * 128, wr0 = wid * 16;

    const __nv_bfloat16* bg = g_bias + ((size_t)(h * N_ + row0)) * N_;

    // Q fragments for 2 batches
    uint32_t qa[2][2][4];
#pragma unroll
    for (int bb = 0; bb < 2; ++bb) {
        const __half* qg = g_qh + ((size_t)(((b0i + bb) * H_ + h) * N_ + row0 + wr0)) * D_;
#pragma unroll
        for (int kk = 0; kk < 2; ++kk) {
            qa[bb][kk][0] = *(const uint32_t*)(qg + g * 32 + 16 * kk + 2 * i);
            qa[bb][kk][1] = *(const uint32_t*)(qg + (g + 8) * 32 + 16 * kk + 2 * i);
            qa[bb][kk][2] = *(const uint32_t*)(qg + g * 32 + 16 * kk + 2 * i + 8);
            qa[bb][kk][3] = *(const uint32_t*)(qg + (g + 8) * 32 + 16 * kk + 2 * i + 8);
        }
    }

    float oc[2][4][4];
    float mr[2][2], lr[2][2];
#pragma unroll
    for (int bb = 0; bb < 2; ++bb) {
        mr[bb][0] = -1e30f; mr[bb][1] = -1e30f;
        lr[bb][0] = 0.0f;   lr[bb][1] = 0.0f;
#pragma unroll
        for (int nt = 0; nt < 4; ++nt)
#pragma unroll
            for (int q = 0; q < 4; ++q) oc[bb][nt][q] = 0.0f;
    }

    for (int cc = 0; cc < 32; ++cc) {
        const int cb = cc * 64;
        __syncthreads();
        // stage K (row-major fp16) and V (transposed) for 2 batches
#pragma unroll
        for (int it = 0; it < 2; ++it) {
            const int idx = tid + 256 * it;
            const int bb = idx >> 8, j = (idx >> 2) & 63, seg = idx & 3;
            const size_t go = ((size_t)(((b0i + bb) * H_ + h) * N_ + cb + j)) * D_ + seg * 8;
            uint4 kv = *(const uint4*)(g_kh + go);
            *(uint4*)(Ks + (bb * 64 + j) * LDK + seg * 8) = kv;
            uint4 vv = *(const uint4*)(g_vh + go);
            __half* vb = Vt + (bb * 32 + seg * 8) * LDV + j;
            vb[0 * LDV] = __ushort_as_half((unsigned short)(vv.x & 0xFFFF));
            vb[1 * LDV] = __ushort_as_half((unsigned short)(vv.x >> 16));
            vb[2 * LDV] = __ushort_as_half((unsigned short)(vv.y & 0xFFFF));
            vb[3 * LDV] = __ushort_as_half((unsigned short)(vv.y >> 16));
            vb[4 * LDV] = __ushort_as_half((unsigned short)(vv.z & 0xFFFF));
            vb[5 * LDV] = __ushort_as_half((unsigned short)(vv.z >> 16));
            vb[6 * LDV] = __ushort_as_half((unsigned short)(vv.w & 0xFFFF));
            vb[7 * LDV] = __ushort_as_half((unsigned short)(vv.w >> 16));
        }
        // stage bias tile 128x64 bf16
#pragma unroll
        for (int it = 0; it < 4; ++it) {
            const int idx = tid + 256 * it;
            const int r = idx >> 3, c8 = (idx & 7) << 3;
            uint4 bb4 = *(const uint4*)(bg + (size_t)r * N_ + cb + c8);
            *(uint4*)(Bsm + r * 72 + c8) = bb4;
        }
        __syncthreads();

#pragma unroll
        for (int bb = 0; bb < 2; ++bb) {
            // S = bias + Q K^T
            float cS[8][4];
#pragma unroll
            for (int jt = 0; jt < 8; ++jt) {
                __nv_bfloat162 t0 = *(__nv_bfloat162*)(Bsm + (wr0 + g) * 72 + 8 * jt + 2 * i);
                __nv_bfloat162 t1 = *(__nv_bfloat162*)(Bsm + (wr0 + g + 8) * 72 + 8 * jt + 2 * i);
                float2 f0 = __bfloat1622float2(t0);
                float2 f1 = __bfloat1622float2(t1);
                cS[jt][0] = f0.x; cS[jt][1] = f0.y;
                cS[jt][2] = f1.x; cS[jt][3] = f1.y;
            }
#pragma unroll
            for (int jt = 0; jt < 8; ++jt) {
#pragma unroll
                for (int kk = 0; kk < 2; ++kk) {
                    const __half* kp = Ks + (bb * 64 + 8 * jt + g) * LDK + 16 * kk + 2 * i;
                    uint32_t b0 = *(const uint32_t*)kp;
                    uint32_t b1 = *(const uint32_t*)(kp + 8);
                    mma_f16(cS[jt], qa[bb][kk][0], qa[bb][kk][1],
                            qa[bb][kk][2], qa[bb][kk][3], b0, b1);
                }
            }
            // online softmax
            float mx0 = -1e30f, mx1 = -1e30f;
#pragma unroll
            for (int jt = 0; jt < 8; ++jt) {
                mx0 = fmaxf(mx0, fmaxf(cS[jt][0], cS[jt][1]));
                mx1 = fmaxf(mx1, fmaxf(cS[jt][2], cS[jt][3]));
            }
            mx0 = fmaxf(mx0, __shfl_xor_sync(0xffffffffu, mx0, 1));
            mx0 = fmaxf(mx0, __shfl_xor_sync(0xffffffffu, mx0, 2));
            mx1 = fmaxf(mx1, __shfl_xor_sync(0xffffffffu, mx1, 1));
            mx1 = fmaxf(mx1, __shfl_xor_sync(0xffffffffu, mx1, 2));
            const float nm0 = fmaxf(mr[bb][0], mx0), nm1 = fmaxf(mr[bb][1], mx1);
            const float al0 = __expf(mr[bb][0] - nm0), al1 = __expf(mr[bb][1] - nm1);
            float s0 = 0.0f, s1 = 0.0f;
#pragma unroll
            for (int jt = 0; jt < 8; ++jt) {
                cS[jt][0] = __expf(cS[jt][0] - nm0);
                cS[jt][1] = __expf(cS[jt][1] - nm0);
                cS[jt][2] = __expf(cS[jt][2] - nm1);
                cS[jt][3] = __expf(cS[jt][3] - nm1);
                s0 += cS[jt][0] + cS[jt][1];
                s1 += cS[jt][2] + cS[jt][3];
            }
            s0 += __shfl_xor_sync(0xffffffffu, s0, 1);
            s0 += __shfl_xor_sync(0xffffffffu, s0, 2);
            s1 += __shfl_xor_sync(0xffffffffu, s1, 1);
            s1 += __shfl_xor_sync(0xffffffffu, s1, 2);
            lr[bb][0] = lr[bb][0] * al0 + s0;
            lr[bb][1] = lr[bb][1] * al1 + s1;
            mr[bb][0] = nm0; mr[bb][1] = nm1;
#pragma unroll
            for (int nt = 0; nt < 4; ++nt) {
                oc[bb][nt][0] *= al0; oc[bb][nt][1] *= al0;
                oc[bb][nt][2] *= al1; oc[bb][nt][3] *= al1;
            }
            // O += P V
#pragma unroll
            for (int kt = 0; kt < 4; ++kt) {
                uint32_t a0 = packh2(cS[2 * kt][0], cS[2 * kt][1]);
                uint32_t a1 = packh2(cS[2 * kt][2], cS[2 * kt][3]);
                uint32_t a2 = packh2(cS[2 * kt + 1][0], cS[2 * kt + 1][1]);
                uint32_t a3 = packh2(cS[2 * kt + 1][2], cS[2 * kt + 1][3]);
#pragma unroll
                for (int nt = 0; nt < 4; ++nt) {
                    const __half* vp = Vt + (bb * 32 + 8 * nt + g) * LDV + 16 * kt + 2 * i;
                    uint32_t b0 = *(const uint32_t*)vp;
                    uint32_t b1 = *(const uint32_t*)(vp + 8);
                    mma_f16(oc[bb][nt], a0, a1, a2, a3, b0, b1);
                }
            }
        }
    }

    // epilogue
#pragma unroll
    for (int bb = 0; bb < 2; ++bb) {
        const float r0 = 1.0f / lr[bb][0], r1 = 1.0f / lr[bb][1];
        const int gr = row0 + wr0 + g;
#pragma unroll
        for (int nt = 0; nt < 4; ++nt) {
            const int col = h * D_ + 8 * nt + 2 * i;
            *(float2*)(g_ao + (size_t)((b0i + bb) * N_ + gr) * C_ + col) =
                make_float2(oc[bb][nt][0] * r0, oc[bb][nt][1] * r0);
            *(float2*)(g_ao + (size_t)((b0i + bb) * N_ + gr + 8) * C_ + col) =
                make_float2(oc[bb][nt][2] * r1, oc[bb][nt][3] * r1);
        }
    }
}

// =====================================================================
extern "C" void kernel_launch(void* const* d_in, const int* in_sizes, int n_in,
                              void* d_out, int out_size)
{
    const float* x          = (const float*)d_in[0];
    const float* w_qkv      = (const float*)d_in[1];
    const float* bias_table = (const float*)d_in[2];
    const float* w_out      = (const float*)d_in[3];
    const float* b_out      = (const float*)d_in[4];
    const int*   rel_index  = (const int*)d_in[5];
    float* out = (float*)d_out;

    k_gemm_tf32<768, 0><<<dim3(12, 64), 256>>>(x, w_qkv, nullptr, nullptr);
    k_bias_gather<<<(N_ * N_ / 4) / 256, 256>>>(rel_index, bias_table);
    k_attn2<<<dim3(16, 8, 2), 256>>>();
    // WHICH=1 binds A := g_ao inside device code (no host ref to device symbol)
    k_gemm_tf32<256, 1><<<dim3(4, 64), 256>>>(nullptr, w_out, b_out, out);
}

// round 9
// speedup vs baseline: 4.0826x; 1.1763x over previous
#include <cuda_runtime.h>
#include <cuda_bf16.h>
#include <cuda_fp16.h>
#include <cstdint>
#include <cstddef>

#define B_  4
#define N_  2048
#define C_  256
#define H_  8
#define D_  32
#define QK_SCALE 0.17677669529663689f

// ---------------- scratch ----------------
__device__ __half g_qh[(size_t)B_ * H_ * N_ * D_];   // pre-scaled
__device__ __half g_kh[(size_t)B_ * H_ * N_ * D_];
__device__ __half g_vh[(size_t)B_ * H_ * N_ * D_];
__device__ __nv_bfloat16 g_bias[(size_t)H_ * N_ * N_];
__device__ float g_ao[(size_t)B_ * N_ * C_];

// ---------------- mma helpers ----------------
__device__ __forceinline__ uint32_t f2tf32(float f) {
    uint32_t r;
    asm("cvt.rna.tf32.f32 %0, %1;" : "=r"(r) : "f"(f));
    return r;
}
__device__ __forceinline__ float tf32hi(float f) {
    return __uint_as_float(f2tf32(f));
}
__device__ __forceinline__ void mma_tf32(float* c, const uint32_t* a,
                                         uint32_t b0, uint32_t b1) {
    asm("mma.sync.aligned.m16n8k8.row.col.f32.tf32.tf32.f32 "
        "{%0,%1,%2,%3},{%4,%5,%6,%7},{%8,%9},{%0,%1,%2,%3};"
        : "+f"(c[0]), "+f"(c[1]), "+f"(c[2]), "+f"(c[3])
        : "r"(a[0]), "r"(a[1]), "r"(a[2]), "r"(a[3]), "r"(b0), "r"(b1));
}
__device__ __forceinline__ void mma_f16(float* c, uint32_t a0, uint32_t a1,
                                        uint32_t a2, uint32_t a3,
                                        uint32_t b0, uint32_t b1) {
    asm("mma.sync.aligned.m16n8k16.row.col.f32.f16.f16.f32 "
        "{%0,%1,%2,%3},{%4,%5,%6,%7},{%8,%9},{%0,%1,%2,%3};"
        : "+f"(c[0]), "+f"(c[1]), "+f"(c[2]), "+f"(c[3])
        : "r"(a0), "r"(a1), "r"(a2), "r"(a3), "r"(b0), "r"(b1));
}
__device__ __forceinline__ uint32_t packh2(float x, float y) {
    uint32_t r;
    asm("cvt.rn.f16x2.f32 %0, %1, %2;" : "=r"(r) : "f"(y), "f"(x));
    return r;
}
__device__ __forceinline__ uint32_t bfpack(float x, float y) {
    __nv_bfloat162 t = __floats2bfloat162_rn(x, y);
    return *(uint32_t*)&t;
}

// =====================================================================
// tf32 GEMM: A(Mx256) @ B(256xN), block 128x64, 8 warps (4M x 2N)
// X3=1: tf32x3 error-compensated. X3=0: single-pass tf32.
// WHICH=0: A from param, QKV epilogue (fp16 scatter).
// WHICH=1: A = g_ao (bound in DEVICE code), out + bias epilogue (fp32).
// =====================================================================
template<int BSTRIDE, int WHICH, int X3>
__global__ __launch_bounds__(256) void k_gemm_tf32(
    const float* __restrict__ A, const float* __restrict__ Bw,
    const float* __restrict__ bias, float* __restrict__ out)
{
    __shared__ float Ah[16 * 136];
    __shared__ float Bh[16 * 72];
    __shared__ float Al[X3 ? 16 * 136 : 1];
    __shared__ float Bl[X3 ? 16 * 72 : 1];

    const float* __restrict__ Asrc = (WHICH == 1) ? (const float*)g_ao : A;

    const int tid = threadIdx.x, wid = tid >> 5, lane = tid & 31;
    const int g = lane >> 2, i = lane & 3;
    const int bx = blockIdx.x, by = blockIdx.y;
    const int wm = (wid & 3) * 32, wn = (wid >> 2) * 32;

    float acc[2][4][4];
#pragma unroll
    for (int mt = 0; mt < 2; ++mt)
#pragma unroll
        for (int nt = 0; nt < 4; ++nt)
#pragma unroll
            for (int q = 0; q < 4; ++q) acc[mt][nt][q] = 0.0f;

    for (int kc = 0; kc < 256; kc += 16) {
        __syncthreads();
#pragma unroll
        for (int it = 0; it < 2; ++it) {
            const int f = tid + 256 * it;
            const int r = f >> 2, c4 = (f & 3) * 4;
            float4 av = *(const float4*)(Asrc + (size_t)(by * 128 + r) * 256 + kc + c4);
            float h0 = tf32hi(av.x), h1 = tf32hi(av.y);
            float h2 = tf32hi(av.z), h3 = tf32hi(av.w);
            Ah[(c4 + 0) * 136 + r] = h0;
            Ah[(c4 + 1) * 136 + r] = h1;
            Ah[(c4 + 2) * 136 + r] = h2;
            Ah[(c4 + 3) * 136 + r] = h3;
            if (X3) {
                Al[(c4 + 0) * 136 + r] = tf32hi(av.x - h0);
                Al[(c4 + 1) * 136 + r] = tf32hi(av.y - h1);
                Al[(c4 + 2) * 136 + r] = tf32hi(av.z - h2);
                Al[(c4 + 3) * 136 + r] = tf32hi(av.w - h3);
            }
        }
        {
            const int kr = tid >> 4, nc4 = (tid & 15) * 4;
            float4 bv = *(const float4*)(Bw + (size_t)(kc + kr) * BSTRIDE + bx * 64 + nc4);
            float4 hv;
            hv.x = tf32hi(bv.x); hv.y = tf32hi(bv.y);
            hv.z = tf32hi(bv.z); hv.w = tf32hi(bv.w);
            *(float4*)(Bh + kr * 72 + nc4) = hv;
            if (X3) {
                float4 lv;
                lv.x = tf32hi(bv.x - hv.x); lv.y = tf32hi(bv.y - hv.y);
                lv.z = tf32hi(bv.z - hv.z); lv.w = tf32hi(bv.w - hv.w);
                *(float4*)(Bl + kr * 72 + nc4) = lv;
            }
        }
        __syncthreads();
#pragma unroll
        for (int s = 0; s < 2; ++s) {
            uint32_t ah[2][4], al[2][4];
#pragma unroll
            for (int mt = 0; mt < 2; ++mt) {
                const int mr = wm + 16 * mt + g;
                ah[mt][0] = __float_as_uint(Ah[(8 * s + i) * 136 + mr]);
                ah[mt][1] = __float_as_uint(Ah[(8 * s + i) * 136 + mr + 8]);
                ah[mt][2] = __float_as_uint(Ah[(8 * s + i + 4) * 136 + mr]);
                ah[mt][3] = __float_as_uint(Ah[(8 * s + i + 4) * 136 + mr + 8]);
                if (X3) {
                    al[mt][0] = __float_as_uint(Al[(8 * s + i) * 136 + mr]);
                    al[mt][1] = __float_as_uint(Al[(8 * s + i) * 136 + mr + 8]);
                    al[mt][2] = __float_as_uint(Al[(8 * s + i + 4) * 136 + mr]);
                    al[mt][3] = __float_as_uint(Al[(8 * s + i + 4) * 136 + mr + 8]);
                }
            }
            uint32_t bh[4][2], bl[4][2];
#pragma unroll
            for (int nt = 0; nt < 4; ++nt) {
                const int nc = wn + 8 * nt + g;
                bh[nt][0] = __float_as_uint(Bh[(8 * s + i) * 72 + nc]);
                bh[nt][1] = __float_as_uint(Bh[(8 * s + i + 4) * 72 + nc]);
                if (X3) {
                    bl[nt][0] = __float_as_uint(Bl[(8 * s + i) * 72 + nc]);
                    bl[nt][1] = __float_as_uint(Bl[(8 * s + i + 4) * 72 + nc]);
                }
            }
#pragma unroll
            for (int mt = 0; mt < 2; ++mt)
#pragma unroll
                for (int nt = 0; nt < 4; ++nt) {
                    mma_tf32(acc[mt][nt], ah[mt], bh[nt][0], bh[nt][1]);
                    if (X3) {
                        mma_tf32(acc[mt][nt], ah[mt], bl[nt][0], bl[nt][1]);
                        mma_tf32(acc[mt][nt], al[mt], bh[nt][0], bh[nt][1]);
                    }
                }
        }
    }

    if (WHICH == 0) {
        // scatter to fp16 q/k/v [b][h][n][d], scale q
#pragma unroll
        for (int nt = 0; nt < 4; ++nt) {
            const int col = bx * 64 + wn + 8 * nt + 2 * i;
            const int which = col >> 8;
            const int cq = col & 255;
            const int hh = cq >> 5, dd = cq & 31;
            const float fac = (which == 0) ? QK_SCALE : 1.0f;
            __half* dst = (which == 0) ? g_qh : (which == 1) ? g_kh : g_vh;
#pragma unroll
            for (int mt = 0; mt < 2; ++mt) {
                const int m = by * 128 + wm + 16 * mt + g;
                const int b = m >> 11, n = m & (N_ - 1);
                __half* p0 = dst + ((size_t)((b * H_ + hh) * N_ + n)) * D_ + dd;
                __half* p1 = dst + ((size_t)((b * H_ + hh) * N_ + n + 8)) * D_ + dd;
                *(__half2*)p0 = __floats2half2_rn(acc[mt][nt][0] * fac, acc[mt][nt][1] * fac);
                *(__half2*)p1 = __floats2half2_rn(acc[mt][nt][2] * fac, acc[mt][nt][3] * fac);
            }
        }
    } else {
#pragma unroll
        for (int nt = 0; nt < 4; ++nt) {
            const int col = bx * 64 + wn + 8 * nt + 2 * i;
            const float bz0 = bias[col], bz1 = bias[col + 1];
#pragma unroll
            for (int mt = 0; mt < 2; ++mt) {
                const int m = by * 128 + wm + 16 * mt + g;
                *(float2*)(out + (size_t)m * 256 + col) =
                    make_float2(acc[mt][nt][0] + bz0, acc[mt][nt][1] + bz1);
                *(float2*)(out + (size_t)(m + 8) * 256 + col) =
                    make_float2(acc[mt][nt][2] + bz0, acc[mt][nt][3] + bz1);
            }
        }
    }
}

// =====================================================================
// bias gather: g_bias[h][n][m] = table[rel[n*N+m]][h], 8 m per thread,
// uint4 (16B) coalesced stores per plane.
// =====================================================================
__global__ __launch_bounds__(256) void k_bias_gather(
    const int* __restrict__ rel, const float* __restrict__ table)
{
    const int t = blockIdx.x * 256 + threadIdx.x;   // 0..524287
    const int n = t >> 8;
    const int m8 = (t & 255) << 3;

    const int* rp = rel + (size_t)n * N_ + m8;
    int4 i0 = *(const int4*)rp;
    int4 i1 = *(const int4*)(rp + 4);
    int ids[8] = {i0.x, i0.y, i0.z, i0.w, i1.x, i1.y, i1.z, i1.w};
    float v[8][8];
#pragma unroll
    for (int q = 0; q < 8; ++q) {
        const float4* tp = (const float4*)(table + (size_t)ids[q] * 8);
        float4 a = tp[0], c = tp[1];
        v[q][0] = a.x; v[q][1] = a.y; v[q][2] = a.z; v[q][3] = a.w;
        v[q][4] = c.x; v[q][5] = c.y; v[q][6] = c.z; v[q][7] = c.w;
    }
    const size_t base = (size_t)n * N_ + m8;
#pragma unroll
    for (int h = 0; h < 8; ++h) {
        uint4 pk = make_uint4(bfpack(v[0][h], v[1][h]),
                              bfpack(v[2][h], v[3][h]),
                              bfpack(v[4][h], v[5][h]),
                              bfpack(v[6][h], v[7][h]));
        *(uint4*)(g_bias + (size_t)h * N_ * N_ + base) = pk;
    }
}

// =====================================================================
// fp16 flash attention, 2 batches fused per block.
// grid (rt=16, h=8, bpair=2), 256 thr, 8 warps x 16 q-rows = 128 rows.
// =====================================================================
#define LDK 40
#define LDV 72

__global__ __launch_bounds__(256) void k_attn2()
{
    __shared__ __half Ks[2 * 64 * LDK];
    __shared__ __half Vt[2 * 32 * LDV];
    __shared__ __nv_bfloat16 Bsm[128 * 72];

    const int tid = threadIdx.x, wid = tid >> 5, lane = tid & 31;
    const int g = lane >> 2, i = lane & 3;
    const int rt = blockIdx.x, h = blockIdx.y, bz = blockIdx.z;
    const int b0i = bz * 2;
    const int row0 = rt * 128, wr0 = wid * 16;

    const __nv_bfloat16* bg = g_bias + ((size_t)(h * N_ + row0)) * N_;

    // Q fragments for 2 batches
    uint32_t qa[2][2][4];
#pragma unroll
    for (int bb = 0; bb < 2; ++bb) {
        const __half* qg = g_qh + ((size_t)(((b0i + bb) * H_ + h) * N_ + row0 + wr0)) * D_;
#pragma unroll
        for (int kk = 0; kk < 2; ++kk) {
            qa[bb][kk][0] = *(const uint32_t*)(qg + g * 32 + 16 * kk + 2 * i);
            qa[bb][kk][1] = *(const uint32_t*)(qg + (g + 8) * 32 + 16 * kk + 2 * i);
            qa[bb][kk][2] = *(const uint32_t*)(qg + g * 32 + 16 * kk + 2 * i + 8);
            qa[bb][kk][3] = *(const uint32_t*)(qg + (g + 8) * 32 + 16 * kk + 2 * i + 8);
        }
    }

    float oc[2][4][4];
    float mr[2][2], lr[2][2];
#pragma unroll
    for (int bb = 0; bb < 2; ++bb) {
        mr[bb][0] = -1e30f; mr[bb][1] = -1e30f;
        lr[bb][0] = 0.0f;   lr[bb][1] = 0.0f;
#pragma unroll
        for (int nt = 0; nt < 4; ++nt)
#pragma unroll
            for (int q = 0; q < 4; ++q) oc[bb][nt][q] = 0.0f;
    }

    for (int cc = 0; cc < 32; ++cc) {
        const int cb = cc * 64;
        __syncthreads();
        // stage K (row-major fp16) and V (transposed) for 2 batches
#pragma unroll
        for (int it = 0; it < 2; ++it) {
            const int idx = tid + 256 * it;
            const int bb = idx >> 8, j = (idx >> 2) & 63, seg = idx & 3;
            const size_t go = ((size_t)(((b0i + bb) * H_ + h) * N_ + cb + j)) * D_ + seg * 8;
            uint4 kv = *(const uint4*)(g_kh + go);
            *(uint4*)(Ks + (bb * 64 + j) * LDK + seg * 8) = kv;
            uint4 vv = *(const uint4*)(g_vh + go);
            __half* vb = Vt + (bb * 32 + seg * 8) * LDV + j;
            vb[0 * LDV] = __ushort_as_half((unsigned short)(vv.x & 0xFFFF));
            vb[1 * LDV] = __ushort_as_half((unsigned short)(vv.x >> 16));
            vb[2 * LDV] = __ushort_as_half((unsigned short)(vv.y & 0xFFFF));
            vb[3 * LDV] = __ushort_as_half((unsigned short)(vv.y >> 16));
            vb[4 * LDV] = __ushort_as_half((unsigned short)(vv.z & 0xFFFF));
            vb[5 * LDV] = __ushort_as_half((unsigned short)(vv.z >> 16));
            vb[6 * LDV] = __ushort_as_half((unsigned short)(vv.w & 0xFFFF));
            vb[7 * LDV] = __ushort_as_half((unsigned short)(vv.w >> 16));
        }
        // stage bias tile 128x64 bf16
#pragma unroll
        for (int it = 0; it < 4; ++it) {
            const int idx = tid + 256 * it;
            const int r = idx >> 3, c8 = (idx & 7) << 3;
            uint4 bb4 = *(const uint4*)(bg + (size_t)r * N_ + cb + c8);
            *(uint4*)(Bsm + r * 72 + c8) = bb4;
        }
        __syncthreads();

#pragma unroll
        for (int bb = 0; bb < 2; ++bb) {
            // S = bias + Q K^T
            float cS[8][4];
#pragma unroll
            for (int jt = 0; jt < 8; ++jt) {
                __nv_bfloat162 t0 = *(__nv_bfloat162*)(Bsm + (wr0 + g) * 72 + 8 * jt + 2 * i);
                __nv_bfloat162 t1 = *(__nv_bfloat162*)(Bsm + (wr0 + g + 8) * 72 + 8 * jt + 2 * i);
                float2 f0 = __bfloat1622float2(t0);
                float2 f1 = __bfloat1622float2(t1);
                cS[jt][0] = f0.x; cS[jt][1] = f0.y;
                cS[jt][2] = f1.x; cS[jt][3] = f1.y;
            }
#pragma unroll
            for (int jt = 0; jt < 8; ++jt) {
#pragma unroll
                for (int kk = 0; kk < 2; ++kk) {
                    const __half* kp = Ks + (bb * 64 + 8 * jt + g) * LDK + 16 * kk + 2 * i;
                    uint32_t b0 = *(const uint32_t*)kp;
                    uint32_t b1 = *(const uint32_t*)(kp + 8);
                    mma_f16(cS[jt], qa[bb][kk][0], qa[bb][kk][1],
                            qa[bb][kk][2], qa[bb][kk][3], b0, b1);
                }
            }
            // online softmax
            float mx0 = -1e30f, mx1 = -1e30f;
#pragma unroll
            for (int jt = 0; jt < 8; ++jt) {
                mx0 = fmaxf(mx0, fmaxf(cS[jt][0], cS[jt][1]));
                mx1 = fmaxf(mx1, fmaxf(cS[jt][2], cS[jt][3]));
            }
            mx0 = fmaxf(mx0, __shfl_xor_sync(0xffffffffu, mx0, 1));
            mx0 = fmaxf(mx0, __shfl_xor_sync(0xffffffffu, mx0, 2));
            mx1 = fmaxf(mx1, __shfl_xor_sync(0xffffffffu, mx1, 1));
            mx1 = fmaxf(mx1, __shfl_xor_sync(0xffffffffu, mx1, 2));
            const float nm0 = fmaxf(mr[bb][0], mx0), nm1 = fmaxf(mr[bb][1], mx1);
            const float al0 = __expf(mr[bb][0] - nm0), al1 = __expf(mr[bb][1] - nm1);
            float s0 = 0.0f, s1 = 0.0f;
#pragma unroll
            for (int jt = 0; jt < 8; ++jt) {
                cS[jt][0] = __expf(cS[jt][0] - nm0);
                cS[jt][1] = __expf(cS[jt][1] - nm0);
                cS[jt][2] = __expf(cS[jt][2] - nm1);
                cS[jt][3] = __expf(cS[jt][3] - nm1);
                s0 += cS[jt][0] + cS[jt][1];
                s1 += cS[jt][2] + cS[jt][3];
            }
            s0 += __shfl_xor_sync(0xffffffffu, s0, 1);
            s0 += __shfl_xor_sync(0xffffffffu, s0, 2);
            s1 += __shfl_xor_sync(0xffffffffu, s1, 1);
            s1 += __shfl_xor_sync(0xffffffffu, s1, 2);
            lr[bb][0] = lr[bb][0] * al0 + s0;
            lr[bb][1] = lr[bb][1] * al1 + s1;
            mr[bb][0] = nm0; mr[bb][1] = nm1;
#pragma unroll
            for (int nt = 0; nt < 4; ++nt) {
                oc[bb][nt][0] *= al0; oc[bb][nt][1] *= al0;
                oc[bb][nt][2] *= al1; oc[bb][nt][3] *= al1;
            }
            // O += P V
#pragma unroll
            for (int kt = 0; kt < 4; ++kt) {
                uint32_t a0 = packh2(cS[2 * kt][0], cS[2 * kt][1]);
                uint32_t a1 = packh2(cS[2 * kt][2], cS[2 * kt][3]);
                uint32_t a2 = packh2(cS[2 * kt + 1][0], cS[2 * kt + 1][1]);
                uint32_t a3 = packh2(cS[2 * kt + 1][2], cS[2 * kt + 1][3]);
#pragma unroll
                for (int nt = 0; nt < 4; ++nt) {
                    const __half* vp = Vt + (bb * 32 + 8 * nt + g) * LDV + 16 * kt + 2 * i;
                    uint32_t b0 = *(const uint32_t*)vp;
                    uint32_t b1 = *(const uint32_t*)(vp + 8);
                    mma_f16(oc[bb][nt], a0, a1, a2, a3, b0, b1);
                }
            }
        }
    }

    // epilogue
#pragma unroll
    for (int bb = 0; bb < 2; ++bb) {
        const float r0 = 1.0f / lr[bb][0], r1 = 1.0f / lr[bb][1];
        const int gr = row0 + wr0 + g;
#pragma unroll
        for (int nt = 0; nt < 4; ++nt) {
            const int col = h * D_ + 8 * nt + 2 * i;
            *(float2*)(g_ao + (size_t)((b0i + bb) * N_ + gr) * C_ + col) =
                make_float2(oc[bb][nt][0] * r0, oc[bb][nt][1] * r0);
            *(float2*)(g_ao + (size_t)((b0i + bb) * N_ + gr + 8) * C_ + col) =
                make_float2(oc[bb][nt][2] * r1, oc[bb][nt][3] * r1);
        }
    }
}

// =====================================================================
extern "C" void kernel_launch(void* const* d_in, const int* in_sizes, int n_in,
                              void* d_out, int out_size)
{
    const float* x          = (const float*)d_in[0];
    const float* w_qkv      = (const float*)d_in[1];
    const float* bias_table = (const float*)d_in[2];
    const float* w_out      = (const float*)d_in[3];
    const float* b_out      = (const float*)d_in[4];
    const int*   rel_index  = (const int*)d_in[5];
    float* out = (float*)d_out;

    k_gemm_tf32<768, 0, 0><<<dim3(12, 64), 256>>>(x, w_qkv, nullptr, nullptr);
    k_bias_gather<<<(N_ * N_ / 8) / 256, 256>>>(rel_index, bias_table);
    k_attn2<<<dim3(16, 8, 2), 256>>>();
    // WHICH=1 binds A := g_ao inside device code (no host ref to device symbol)
    k_gemm_tf32<256, 1, 1><<<dim3(4, 64), 256>>>(nullptr, w_out, b_out, out);
}

// round 10
// speedup vs baseline: 4.4554x; 1.0913x over previous
#include <cuda_runtime.h>
#include <cuda_bf16.h>
#include <cuda_fp16.h>
#include <cstdint>
#include <cstddef>

#define B_  4
#define N_  2048
#define C_  256
#define H_  8
#define D_  32
#define QK_SCALE 0.17677669529663689f

// ---------------- scratch ----------------
__device__ __half g_qh[(size_t)B_ * H_ * N_ * D_];   // pre-scaled
__device__ __half g_kh[(size_t)B_ * H_ * N_ * D_];
__device__ __half g_vh[(size_t)B_ * H_ * N_ * D_];
__device__ __nv_bfloat16 g_bias[(size_t)H_ * N_ * N_];
__device__ float g_ao[(size_t)B_ * N_ * C_];

// ---------------- mma helpers ----------------
__device__ __forceinline__ uint32_t f2tf32(float f) {
    uint32_t r;
    asm("cvt.rna.tf32.f32 %0, %1;" : "=r"(r) : "f"(f));
    return r;
}
__device__ __forceinline__ float tf32hi(float f) {
    return __uint_as_float(f2tf32(f));
}
__device__ __forceinline__ void mma_tf32(float* c, const uint32_t* a,
                                         uint32_t b0, uint32_t b1) {
    asm("mma.sync.aligned.m16n8k8.row.col.f32.tf32.tf32.f32 "
        "{%0,%1,%2,%3},{%4,%5,%6,%7},{%8,%9},{%0,%1,%2,%3};"
        : "+f"(c[0]), "+f"(c[1]), "+f"(c[2]), "+f"(c[3])
        : "r"(a[0]), "r"(a[1]), "r"(a[2]), "r"(a[3]), "r"(b0), "r"(b1));
}
__device__ __forceinline__ void mma_f16(float* c, uint32_t a0, uint32_t a1,
                                        uint32_t a2, uint32_t a3,
                                        uint32_t b0, uint32_t b1) {
    asm("mma.sync.aligned.m16n8k16.row.col.f32.f16.f16.f32 "
        "{%0,%1,%2,%3},{%4,%5,%6,%7},{%8,%9},{%0,%1,%2,%3};"
        : "+f"(c[0]), "+f"(c[1]), "+f"(c[2]), "+f"(c[3])
        : "r"(a0), "r"(a1), "r"(a2), "r"(a3), "r"(b0), "r"(b1));
}
__device__ __forceinline__ uint32_t packh2(float x, float y) {
    uint32_t r;
    asm("cvt.rn.f16x2.f32 %0, %1, %2;" : "=r"(r) : "f"(y), "f"(x));
    return r;
}
__device__ __forceinline__ uint32_t bfpack(float x, float y) {
    __nv_bfloat162 t = __floats2bfloat162_rn(x, y);
    return *(uint32_t*)&t;
}

// =====================================================================
// tf32 GEMM: A(Mx256) @ B(256xN), block 128x64, 8 warps (4M x 2N).
// Software-pipelined: LDG for next k-slice issued before compute.
// X3=1: tf32x3 error-compensated. X3=0: single-pass tf32.
// WHICH=0: A from param, QKV epilogue (fp16 scatter).
// WHICH=1: A = g_ao (device-bound), out + bias epilogue (fp32).
// =====================================================================
template<int BSTRIDE, int WHICH, int X3>
__global__ __launch_bounds__(256) void k_gemm_tf32(
    const float* __restrict__ A, const float* __restrict__ Bw,
    const float* __restrict__ bias, float* __restrict__ out)
{
    __shared__ float Ah[16 * 136];
    __shared__ float Bh[16 * 72];
    __shared__ float Al[X3 ? 16 * 136 : 1];
    __shared__ float Bl[X3 ? 16 * 72 : 1];

    const float* __restrict__ Asrc = (WHICH == 1) ? (const float*)g_ao : A;

    const int tid = threadIdx.x, wid = tid >> 5, lane = tid & 31;
    const int g = lane >> 2, i = lane & 3;
    const int bx = blockIdx.x, by = blockIdx.y;
    const int wm = (wid & 3) * 32, wn = (wid >> 2) * 32;

    // loader coords (fixed per thread)
    const int ar0 = tid >> 2, ac4 = (tid & 3) * 4;   // +128 rows on it=1
    const int bkr = tid >> 4, bnc4 = (tid & 15) * 4;

    float acc[2][4][4];
#pragma unroll
    for (int mt = 0; mt < 2; ++mt)
#pragma unroll
        for (int nt = 0; nt < 4; ++nt)
#pragma unroll
            for (int q = 0; q < 4; ++q) acc[mt][nt][q] = 0.0f;

    float4 ra[2], rb;
    {
        ra[0] = *(const float4*)(Asrc + (size_t)(by * 128 + ar0) * 256 + ac4);
        ra[1] = *(const float4*)(Asrc + (size_t)(by * 128 + ar0 + 64) * 256 + ac4);
        rb    = *(const float4*)(Bw + (size_t)bkr * BSTRIDE + bx * 64 + bnc4);
    }

    for (int kc = 0; kc < 256; kc += 16) {
        __syncthreads();
#pragma unroll
        for (int it = 0; it < 2; ++it) {
            const int r = ar0 + 64 * it;
            float4 av = ra[it];
            float h0 = tf32hi(av.x), h1 = tf32hi(av.y);
            float h2 = tf32hi(av.z), h3 = tf32hi(av.w);
            Ah[(ac4 + 0) * 136 + r] = h0;
            Ah[(ac4 + 1) * 136 + r] = h1;
            Ah[(ac4 + 2) * 136 + r] = h2;
            Ah[(ac4 + 3) * 136 + r] = h3;
            if (X3) {
                Al[(ac4 + 0) * 136 + r] = tf32hi(av.x - h0);
                Al[(ac4 + 1) * 136 + r] = tf32hi(av.y - h1);
                Al[(ac4 + 2) * 136 + r] = tf32hi(av.z - h2);
                Al[(ac4 + 3) * 136 + r] = tf32hi(av.w - h3);
            }
        }
        {
            float4 hv;
            hv.x = tf32hi(rb.x); hv.y = tf32hi(rb.y);
            hv.z = tf32hi(rb.z); hv.w = tf32hi(rb.w);
            *(float4*)(Bh + bkr * 72 + bnc4) = hv;
            if (X3) {
                float4 lv;
                lv.x = tf32hi(rb.x - hv.x); lv.y = tf32hi(rb.y - hv.y);
                lv.z = tf32hi(rb.z - hv.z); lv.w = tf32hi(rb.w - hv.w);
                *(float4*)(Bl + bkr * 72 + bnc4) = lv;
            }
        }
        __syncthreads();
        if (kc + 16 < 256) {
            const int kn = kc + 16;
            ra[0] = *(const float4*)(Asrc + (size_t)(by * 128 + ar0) * 256 + kn + ac4);
            ra[1] = *(const float4*)(Asrc + (size_t)(by * 128 + ar0 + 64) * 256 + kn + ac4);
            rb    = *(const float4*)(Bw + (size_t)(kn + bkr) * BSTRIDE + bx * 64 + bnc4);
        }
#pragma unroll
        for (int s = 0; s < 2; ++s) {
            uint32_t ah[2][4], al[2][4];
#pragma unroll
            for (int mt = 0; mt < 2; ++mt) {
                const int mr = wm + 16 * mt + g;
                ah[mt][0] = __float_as_uint(Ah[(8 * s + i) * 136 + mr]);
                ah[mt][1] = __float_as_uint(Ah[(8 * s + i) * 136 + mr + 8]);
                ah[mt][2] = __float_as_uint(Ah[(8 * s + i + 4) * 136 + mr]);
                ah[mt][3] = __float_as_uint(Ah[(8 * s + i + 4) * 136 + mr + 8]);
                if (X3) {
                    al[mt][0] = __float_as_uint(Al[(8 * s + i) * 136 + mr]);
                    al[mt][1] = __float_as_uint(Al[(8 * s + i) * 136 + mr + 8]);
                    al[mt][2] = __float_as_uint(Al[(8 * s + i + 4) * 136 + mr]);
                    al[mt][3] = __float_as_uint(Al[(8 * s + i + 4) * 136 + mr + 8]);
                }
            }
            uint32_t bh[4][2], bl[4][2];
#pragma unroll
            for (int nt = 0; nt < 4; ++nt) {
                const int nc = wn + 8 * nt + g;
                bh[nt][0] = __float_as_uint(Bh[(8 * s + i) * 72 + nc]);
                bh[nt][1] = __float_as_uint(Bh[(8 * s + i + 4) * 72 + nc]);
                if (X3) {
                    bl[nt][0] = __float_as_uint(Bl[(8 * s + i) * 72 + nc]);
                    bl[nt][1] = __float_as_uint(Bl[(8 * s + i + 4) * 72 + nc]);
                }
            }
#pragma unroll
            for (int mt = 0; mt < 2; ++mt)
#pragma unroll
                for (int nt = 0; nt < 4; ++nt) {
                    mma_tf32(acc[mt][nt], ah[mt], bh[nt][0], bh[nt][1]);
                    if (X3) {
                        mma_tf32(acc[mt][nt], ah[mt], bl[nt][0], bl[nt][1]);
                        mma_tf32(acc[mt][nt], al[mt], bh[nt][0], bh[nt][1]);
                    }
                }
        }
    }

    if (WHICH == 0) {
#pragma unroll
        for (int nt = 0; nt < 4; ++nt) {
            const int col = bx * 64 + wn + 8 * nt + 2 * i;
            const int which = col >> 8;
            const int cq = col & 255;
            const int hh = cq >> 5, dd = cq & 31;
            const float fac = (which == 0) ? QK_SCALE : 1.0f;
            __half* dst = (which == 0) ? g_qh : (which == 1) ? g_kh : g_vh;
#pragma unroll
            for (int mt = 0; mt < 2; ++mt) {
                const int m = by * 128 + wm + 16 * mt + g;
                const int b = m >> 11, n = m & (N_ - 1);
                __half* p0 = dst + ((size_t)((b * H_ + hh) * N_ + n)) * D_ + dd;
                __half* p1 = dst + ((size_t)((b * H_ + hh) * N_ + n + 8)) * D_ + dd;
                *(__half2*)p0 = __floats2half2_rn(acc[mt][nt][0] * fac, acc[mt][nt][1] * fac);
                *(__half2*)p1 = __floats2half2_rn(acc[mt][nt][2] * fac, acc[mt][nt][3] * fac);
            }
        }
    } else {
#pragma unroll
        for (int nt = 0; nt < 4; ++nt) {
            const int col = bx * 64 + wn + 8 * nt + 2 * i;
            const float bz0 = bias[col], bz1 = bias[col + 1];
#pragma unroll
            for (int mt = 0; mt < 2; ++mt) {
                const int m = by * 128 + wm + 16 * mt + g;
                *(float2*)(out + (size_t)m * 256 + col) =
                    make_float2(acc[mt][nt][0] + bz0, acc[mt][nt][1] + bz1);
                *(float2*)(out + (size_t)(m + 8) * 256 + col) =
                    make_float2(acc[mt][nt][2] + bz0, acc[mt][nt][3] + bz1);
            }
        }
    }
}

// =====================================================================
// bias gather: g_bias[h][n][m] = table[rel[n*N+m]][h], 8 m per thread
// =====================================================================
__global__ __launch_bounds__(256) void k_bias_gather(
    const int* __restrict__ rel, const float* __restrict__ table)
{
    const int t = blockIdx.x * 256 + threadIdx.x;
    const int n = t >> 8;
    const int m8 = (t & 255) << 3;

    const int* rp = rel + (size_t)n * N_ + m8;
    int4 i0 = *(const int4*)rp;
    int4 i1 = *(const int4*)(rp + 4);
    int ids[8] = {i0.x, i0.y, i0.z, i0.w, i1.x, i1.y, i1.z, i1.w};
    float v[8][8];
#pragma unroll
    for (int q = 0; q < 8; ++q) {
        const float4* tp = (const float4*)(table + (size_t)ids[q] * 8);
        float4 a = tp[0], c = tp[1];
        v[q][0] = a.x; v[q][1] = a.y; v[q][2] = a.z; v[q][3] = a.w;
        v[q][4] = c.x; v[q][5] = c.y; v[q][6] = c.z; v[q][7] = c.w;
    }
    const size_t base = (size_t)n * N_ + m8;
#pragma unroll
    for (int h = 0; h < 8; ++h) {
        uint4 pk = make_uint4(bfpack(v[0][h], v[1][h]),
                              bfpack(v[2][h], v[3][h]),
                              bfpack(v[4][h], v[5][h]),
                              bfpack(v[6][h], v[7][h]));
        *(uint4*)(g_bias + (size_t)h * N_ * N_ + base) = pk;
    }
}

// =====================================================================
// fp16 flash attention, 2 batches fused, software-pipelined staging.
// grid (rt=32, h=8, bpair=2) = 512 blocks, 128 threads (4 warps x 16
// q-rows = 64 rows/block). 3 CTAs/SM target.
// =====================================================================
#define LDK 40
#define LDV 72

__global__ __launch_bounds__(128) void k_attn2()
{
    __shared__ __half Ks[2 * 64 * LDK];          // [bat][key][dim]
    __shared__ __half Vt[2 * 32 * LDV];          // [bat][dim][key]
    __shared__ __nv_bfloat16 Bsm[64 * 72];       // [qrow][key]

    const int tid = threadIdx.x, wid = tid >> 5, lane = tid & 31;
    const int g = lane >> 2, i = lane & 3;
    const int rt = blockIdx.x, h = blockIdx.y, bz = blockIdx.z;
    const int b0i = bz * 2;
    const int row0 = rt * 64, wr0 = wid * 16;

    const __nv_bfloat16* bg = g_bias + ((size_t)(h * N_ + row0)) * N_;

    // per-thread loader coords
    const int l_bb = tid >> 8;                   // always 0 for 128 thr; it adds
    (void)l_bb;

    // Q fragments for 2 batches
    uint32_t qa[2][2][4];
#pragma unroll
    for (int bb = 0; bb < 2; ++bb) {
        const __half* qg = g_qh + ((size_t)(((b0i + bb) * H_ + h) * N_ + row0 + wr0)) * D_;
#pragma unroll
        for (int kk = 0; kk < 2; ++kk) {
            qa[bb][kk][0] = *(const uint32_t*)(qg + g * 32 + 16 * kk + 2 * i);
            qa[bb][kk][1] = *(const uint32_t*)(qg + (g + 8) * 32 + 16 * kk + 2 * i);
            qa[bb][kk][2] = *(const uint32_t*)(qg + g * 32 + 16 * kk + 2 * i + 8);
            qa[bb][kk][3] = *(const uint32_t*)(qg + (g + 8) * 32 + 16 * kk + 2 * i + 8);
        }
    }

    float oc[2][4][4];
    float mr[2][2], lr[2][2];
#pragma unroll
    for (int bb = 0; bb < 2; ++bb) {
        mr[bb][0] = -1e30f; mr[bb][1] = -1e30f;
        lr[bb][0] = 0.0f;   lr[bb][1] = 0.0f;
#pragma unroll
        for (int nt = 0; nt < 4; ++nt)
#pragma unroll
            for (int q = 0; q < 4; ++q) oc[bb][nt][q] = 0.0f;
    }

    // staging registers (prefetch pipeline)
    uint4 pk[4], pv[4], pb[4];

    // prefetch chunk 0
    {
        const int cb = 0;
#pragma unroll
        for (int it = 0; it < 4; ++it) {
            const int idx = tid + 128 * it;
            const int bb = idx >> 8, j = (idx >> 2) & 63, seg = idx & 3;
            const size_t go = ((size_t)(((b0i + bb) * H_ + h) * N_ + cb + j)) * D_ + seg * 8;
            pk[it] = *(const uint4*)(g_kh + go);
            pv[it] = *(const uint4*)(g_vh + go);
        }
#pragma unroll
        for (int it = 0; it < 4; ++it) {
            const int idx = tid + 128 * it;
            const int r = idx >> 3, c8 = (idx & 7) << 3;
            pb[it] = *(const uint4*)(bg + (size_t)r * N_ + cb + c8);
        }
    }

    for (int cc = 0; cc < 32; ++cc) {
        const int cb = cc * 64;
        __syncthreads();
        // store staged regs to smem (K row-major, V transposed, bias)
#pragma unroll
        for (int it = 0; it < 4; ++it) {
            const int idx = tid + 128 * it;
            const int bb = idx >> 8, j = (idx >> 2) & 63, seg = idx & 3;
            *(uint4*)(Ks + (bb * 64 + j) * LDK + seg * 8) = pk[it];
            uint4 vv = pv[it];
            __half* vb = Vt + (bb * 32 + seg * 8) * LDV + j;
            vb[0 * LDV] = __ushort_as_half((unsigned short)(vv.x & 0xFFFF));
            vb[1 * LDV] = __ushort_as_half((unsigned short)(vv.x >> 16));
            vb[2 * LDV] = __ushort_as_half((unsigned short)(vv.y & 0xFFFF));
            vb[3 * LDV] = __ushort_as_half((unsigned short)(vv.y >> 16));
            vb[4 * LDV] = __ushort_as_half((unsigned short)(vv.z & 0xFFFF));
            vb[5 * LDV] = __ushort_as_half((unsigned short)(vv.z >> 16));
            vb[6 * LDV] = __ushort_as_half((unsigned short)(vv.w & 0xFFFF));
            vb[7 * LDV] = __ushort_as_half((unsigned short)(vv.w >> 16));
        }
#pragma unroll
        for (int it = 0; it < 4; ++it) {
            const int idx = tid + 128 * it;
            const int r = idx >> 3, c8 = (idx & 7) << 3;
            *(uint4*)(Bsm + r * 72 + c8) = pb[it];
        }
        __syncthreads();

        // prefetch next chunk (overlaps with compute below)
        if (cc + 1 < 32) {
            const int cn = cb + 64;
#pragma unroll
            for (int it = 0; it < 4; ++it) {
                const int idx = tid + 128 * it;
                const int bb = idx >> 8, j = (idx >> 2) & 63, seg = idx & 3;
                const size_t go = ((size_t)(((b0i + bb) * H_ + h) * N_ + cn + j)) * D_ + seg * 8;
                pk[it] = *(const uint4*)(g_kh + go);
                pv[it] = *(const uint4*)(g_vh + go);
            }
#pragma unroll
            for (int it = 0; it < 4; ++it) {
                const int idx = tid + 128 * it;
                const int r = idx >> 3, c8 = (idx & 7) << 3;
                pb[it] = *(const uint4*)(bg + (size_t)r * N_ + cn + c8);
            }
        }

#pragma unroll
        for (int bb = 0; bb < 2; ++bb) {
            // S = bias + Q K^T
            float cS[8][4];
#pragma unroll
            for (int jt = 0; jt < 8; ++jt) {
                __nv_bfloat162 t0 = *(__nv_bfloat162*)(Bsm + (wr0 + g) * 72 + 8 * jt + 2 * i);
                __nv_bfloat162 t1 = *(__nv_bfloat162*)(Bsm + (wr0 + g + 8) * 72 + 8 * jt + 2 * i);
                float2 f0 = __bfloat1622float2(t0);
                float2 f1 = __bfloat1622float2(t1);
                cS[jt][0] = f0.x; cS[jt][1] = f0.y;
                cS[jt][2] = f1.x; cS[jt][3] = f1.y;
            }
#pragma unroll
            for (int jt = 0; jt < 8; ++jt) {
#pragma unroll
                for (int kk = 0; kk < 2; ++kk) {
                    const __half* kp = Ks + (bb * 64 + 8 * jt + g) * LDK + 16 * kk + 2 * i;
                    uint32_t b0 = *(const uint32_t*)kp;
                    uint32_t b1 = *(const uint32_t*)(kp + 8);
                    mma_f16(cS[jt], qa[bb][kk][0], qa[bb][kk][1],
                            qa[bb][kk][2], qa[bb][kk][3], b0, b1);
                }
            }
            // online softmax
            float mx0 = -1e30f, mx1 = -1e30f;
#pragma unroll
            for (int jt = 0; jt < 8; ++jt) {
                mx0 = fmaxf(mx0, fmaxf(cS[jt][0], cS[jt][1]));
                mx1 = fmaxf(mx1, fmaxf(cS[jt][2], cS[jt][3]));
            }
            mx0 = fmaxf(mx0, __shfl_xor_sync(0xffffffffu, mx0, 1));
            mx0 = fmaxf(mx0, __shfl_xor_sync(0xffffffffu, mx0, 2));
            mx1 = fmaxf(mx1, __shfl_xor_sync(0xffffffffu, mx1, 1));
            mx1 = fmaxf(mx1, __shfl_xor_sync(0xffffffffu, mx1, 2));
            const float nm0 = fmaxf(mr[bb][0], mx0), nm1 = fmaxf(mr[bb][1], mx1);
            const float al0 = __expf(mr[bb][0] - nm0), al1 = __expf(mr[bb][1] - nm1);
            float s0 = 0.0f, s1 = 0.0f;
#pragma unroll
            for (int jt = 0; jt < 8; ++jt) {
                cS[jt][0] = __expf(cS[jt][0] - nm0);
                cS[jt][1] = __expf(cS[jt][1] - nm0);
                cS[jt][2] = __expf(cS[jt][2] - nm1);
                cS[jt][3] = __expf(cS[jt][3] - nm1);
                s0 += cS[jt][0] + cS[jt][1];
                s1 += cS[jt][2] + cS[jt][3];
            }
            s0 += __shfl_xor_sync(0xffffffffu, s0, 1);
            s0 += __shfl_xor_sync(0xffffffffu, s0, 2);
            s1 += __shfl_xor_sync(0xffffffffu, s1, 1);
            s1 += __shfl_xor_sync(0xffffffffu, s1, 2);
            lr[bb][0] = lr[bb][0] * al0 + s0;
            lr[bb][1] = lr[bb][1] * al1 + s1;
            mr[bb][0] = nm0; mr[bb][1] = nm1;
#pragma unroll
            for (int nt = 0; nt < 4; ++nt) {
                oc[bb][nt][0] *= al0; oc[bb][nt][1] *= al0;
                oc[bb][nt][2] *= al1; oc[bb][nt][3] *= al1;
            }
            // O += P V
#pragma unroll
            for (int kt = 0; kt < 4; ++kt) {
                uint32_t a0 = packh2(cS[2 * kt][0], cS[2 * kt][1]);
                uint32_t a1 = packh2(cS[2 * kt][2], cS[2 * kt][3]);
                uint32_t a2 = packh2(cS[2 * kt + 1][0], cS[2 * kt + 1][1]);
                uint32_t a3 = packh2(cS[2 * kt + 1][2], cS[2 * kt + 1][3]);
#pragma unroll
                for (int nt = 0; nt < 4; ++nt) {
                    const __half* vp = Vt + (bb * 32 + 8 * nt + g) * LDV + 16 * kt + 2 * i;
                    uint32_t b0 = *(const uint32_t*)vp;
                    uint32_t b1 = *(const uint32_t*)(vp + 8);
                    mma_f16(oc[bb][nt], a0, a1, a2, a3, b0, b1);
                }
            }
        }
    }

    // epilogue
#pragma unroll
    for (int bb = 0; bb < 2; ++bb) {
        const float r0 = 1.0f / lr[bb][0], r1 = 1.0f / lr[bb][1];
        const int gr = row0 + wr0 + g;
#pragma unroll
        for (int nt = 0; nt < 4; ++nt) {
            const int col = h * D_ + 8 * nt + 2 * i;
            *(float2*)(g_ao + (size_t)((b0i + bb) * N_ + gr) * C_ + col) =
                make_float2(oc[bb][nt][0] * r0, oc[bb][nt][1] * r0);
            *(float2*)(g_ao + (size_t)((b0i + bb) * N_ + gr + 8) * C_ + col) =
                make_float2(oc[bb][nt][2] * r1, oc[bb][nt][3] * r1);
        }
    }
}

// =====================================================================
extern "C" void kernel_launch(void* const* d_in, const int* in_sizes, int n_in,
                              void* d_out, int out_size)
{
    const float* x          = (const float*)d_in[0];
    const float* w_qkv      = (const float*)d_in[1];
    const float* bias_table = (const float*)d_in[2];
    const float* w_out      = (const float*)d_in[3];
    const float* b_out      = (const float*)d_in[4];
    const int*   rel_index  = (const int*)d_in[5];
    float* out = (float*)d_out;

    k_gemm_tf32<768, 0, 0><<<dim3(12, 64), 256>>>(x, w_qkv, nullptr, nullptr);
    k_bias_gather<<<(N_ * N_ / 8) / 256, 256>>>(rel_index, bias_table);
    k_attn2<<<dim3(32, 8, 2), 128>>>();
    k_gemm_tf32<256, 1, 1><<<dim3(4, 64), 256>>>(nullptr, w_out, b_out, out);
}